// round 7
// baseline (speedup 1.0000x reference)
#include <cuda_runtime.h>
#include <math.h>

#define NSEQ  256
#define LRES  384
#define MDIM  256
#define NHEAD 8
#define CDIM  32
#define HC    256
#define NL    (NSEQ * LRES)            // 98304
#define SQC   0.17677669529663687f     // 1/sqrt(32)

// -------- scratch (static device globals; no allocations allowed) --------
__device__ float g_x[(size_t)NL * MDIM];   // layernormed input
__device__ float g_q[(size_t)NL * HC];
__device__ float g_k[(size_t)NL * HC];
__device__ float g_v[(size_t)NL * HC];
__device__ float g_g[(size_t)NL * HC];     // sigmoid gate (activation applied)
__device__ float g_o[(size_t)NL * HC];     // gated attention output

// ============================ LayerNorm ============================
// one block (64 threads) per row of 256; float4 per thread
__global__ void ln_kernel(const float* __restrict__ m,
                          const float* __restrict__ gamma,
                          const float* __restrict__ beta) {
    int row = blockIdx.x;
    const float4* mr = (const float4*)(m + (size_t)row * MDIM);
    float4* xr = (float4*)(g_x + (size_t)row * MDIM);
    int tid = threadIdx.x;

    float4 v = mr[tid];
    float s  = v.x + v.y + v.z + v.w;
    float ss = v.x * v.x + v.y * v.y + v.z * v.z + v.w * v.w;
    #pragma unroll
    for (int o = 16; o; o >>= 1) {
        s  += __shfl_xor_sync(0xffffffffu, s,  o);
        ss += __shfl_xor_sync(0xffffffffu, ss, o);
    }
    __shared__ float sh[4];
    if ((tid & 31) == 0) { sh[tid >> 5] = s; sh[2 + (tid >> 5)] = ss; }
    __syncthreads();
    s  = sh[0] + sh[1];
    ss = sh[2] + sh[3];
    float mu  = s * (1.0f / MDIM);
    float var = ss * (1.0f / MDIM) - mu * mu;
    float inv = rsqrtf(var + 1e-5f);

    float4 gm = ((const float4*)gamma)[tid];
    float4 bt = ((const float4*)beta)[tid];
    float4 r;
    r.x = (v.x - mu) * inv * gm.x + bt.x;
    r.y = (v.y - mu) * inv * gm.y + bt.y;
    r.z = (v.z - mu) * inv * gm.z + bt.z;
    r.w = (v.w - mu) * inv * gm.w + bt.w;
    xr[tid] = r;
}

// ============================ GEMM ============================
// C[M,256] = A[M,256] * B[256,256]   (A,B,C row-major)
// epi_mode: 0 plain, 1 sigmoid(v + bias), 2 v + bias
#define BM 64
#define BN 64
#define BK 16
__global__ void gemm_kernel(const float* __restrict__ A,
                            const float* __restrict__ B,
                            const float* __restrict__ bias,
                            float* __restrict__ Cout,
                            int epi_mode) {
    __shared__ float As[BK][BM];
    __shared__ float Bs[BK][BN];

    int bn = blockIdx.x * BN;
    int bm = blockIdx.y * BM;
    int tid = threadIdx.x;                 // 256 threads
    int tx = tid & 15, ty = tid >> 4;

    float acc[4][4] = {};

    int ar = tid >> 2;                     // 0..63 (A row within tile)
    int ac = (tid & 3) << 2;               // 0,4,8,12 (A k-offset)
    int br = tid >> 4;                     // 0..15 (B k within tile)
    int bc = (tid & 15) << 2;              // B col offset

    for (int k0 = 0; k0 < 256; k0 += BK) {
        float4 a4 = *(const float4*)&A[(size_t)(bm + ar) * 256 + k0 + ac];
        As[ac + 0][ar] = a4.x;
        As[ac + 1][ar] = a4.y;
        As[ac + 2][ar] = a4.z;
        As[ac + 3][ar] = a4.w;
        *(float4*)&Bs[br][bc] = *(const float4*)&B[(size_t)(k0 + br) * 256 + bn + bc];
        __syncthreads();

        #pragma unroll
        for (int kk = 0; kk < BK; kk++) {
            float4 a = *(float4*)&As[kk][ty << 2];
            float4 b = *(float4*)&Bs[kk][tx << 2];
            acc[0][0] += a.x * b.x; acc[0][1] += a.x * b.y; acc[0][2] += a.x * b.z; acc[0][3] += a.x * b.w;
            acc[1][0] += a.y * b.x; acc[1][1] += a.y * b.y; acc[1][2] += a.y * b.z; acc[1][3] += a.y * b.w;
            acc[2][0] += a.z * b.x; acc[2][1] += a.z * b.y; acc[2][2] += a.z * b.z; acc[2][3] += a.z * b.w;
            acc[3][0] += a.w * b.x; acc[3][1] += a.w * b.y; acc[3][2] += a.w * b.z; acc[3][3] += a.w * b.w;
        }
        __syncthreads();
    }

    #pragma unroll
    for (int i = 0; i < 4; i++) {
        int row = bm + (ty << 2) + i;
        #pragma unroll
        for (int j = 0; j < 4; j++) {
            int col = bn + (tx << 2) + j;
            float val = acc[i][j];
            if (epi_mode == 1)      val = 1.0f / (1.0f + expf(-(val + bias[col])));
            else if (epi_mode == 2) val += bias[col];
            Cout[(size_t)row * 256 + col] = val;
        }
    }
}

// ============================ Attention ============================
// one CTA (256 threads = 8 warps) per (l, h). K and V^T resident in smem.
#define KST 36        // k_sm row stride (floats) — conflict-free float4 reads
#define VST 260       // v^T row stride
#define PST 260       // per-warp softmax prob stride

#define K_SM_F  (256 * KST)                       // 9216
#define V_SM_F  (32 * VST)                        // 8320
#define P_SM_F  (8 * PST)                         // 2080
#define Q_SM_F  (8 * 32)                          // 256
#define ATTN_SMEM_BYTES ((K_SM_F + V_SM_F + P_SM_F + Q_SM_F) * 4)   // 79488

__global__ void attn_kernel() {
    extern __shared__ float sm[];
    float* k_sm = sm;
    float* v_sm = sm + K_SM_F;
    float* p_sm = sm + K_SM_F + V_SM_F;
    float* q_sm = sm + K_SM_F + V_SM_F + P_SM_F;

    int l = blockIdx.x >> 3;
    int h = blockIdx.x & 7;
    int tid = threadIdx.x;
    int w = tid >> 5, lane = tid & 31;

    size_t head_off = (size_t)h * CDIM;

    // load K (256 x 32) and V^T (32 x 256) into smem
    for (int idx = tid; idx < 256 * 32; idx += 256) {
        int t = idx >> 5, c = idx & 31;
        size_t gi = ((size_t)(t * LRES + l)) * HC + head_off + c;
        k_sm[t * KST + c] = g_k[gi];
        v_sm[c * VST + t] = g_v[gi];
    }
    __syncthreads();

    // each warp owns query rows s = w, w+8, ...
    for (int s = w; s < NSEQ; s += 8) {
        size_t qi = ((size_t)(s * LRES + l)) * HC + head_off + lane;
        q_sm[w * 32 + lane] = g_q[qi];
        __syncwarp();

        float sc[8];
        #pragma unroll
        for (int i = 0; i < 8; i++) {
            int t = i * 32 + lane;
            float acc = 0.0f;
            #pragma unroll
            for (int c4 = 0; c4 < 8; c4++) {
                float4 k4 = *(float4*)&k_sm[t * KST + c4 * 4];
                float4 q4 = *(float4*)&q_sm[w * 32 + c4 * 4];
                acc += k4.x * q4.x + k4.y * q4.y + k4.z * q4.z + k4.w * q4.w;
            }
            sc[i] = acc * SQC;
        }
        // softmax over t (256 values spread 8-per-lane)
        float mx = sc[0];
        #pragma unroll
        for (int i = 1; i < 8; i++) mx = fmaxf(mx, sc[i]);
        #pragma unroll
        for (int o = 16; o; o >>= 1) mx = fmaxf(mx, __shfl_xor_sync(0xffffffffu, mx, o));
        float sum = 0.0f;
        #pragma unroll
        for (int i = 0; i < 8; i++) { sc[i] = __expf(sc[i] - mx); sum += sc[i]; }
        #pragma unroll
        for (int o = 16; o; o >>= 1) sum += __shfl_xor_sync(0xffffffffu, sum, o);
        float rinv = 1.0f / sum;
        #pragma unroll
        for (int i = 0; i < 8; i++) p_sm[w * PST + i * 32 + lane] = sc[i] * rinv;
        __syncwarp();

        // out: lane = channel c;  o[c] = sum_t p[t] * v[t][c]
        float acc = 0.0f;
        #pragma unroll
        for (int t4 = 0; t4 < 64; t4++) {
            float4 p4 = *(float4*)&p_sm[w * PST + t4 * 4];
            float4 v4 = *(float4*)&v_sm[lane * VST + t4 * 4];
            acc += p4.x * v4.x + p4.y * v4.y + p4.z * v4.z + p4.w * v4.w;
        }
        float gv = g_g[qi];
        g_o[qi] = acc * gv;
        __syncwarp();
    }
}

// ============================ launch ============================
extern "C" void kernel_launch(void* const* d_in, const int* in_sizes, int n_in,
                              void* d_out, int out_size) {
    (void)in_sizes; (void)n_in; (void)out_size;
    const float* m     = (const float*)d_in[0];
    const float* gamma = (const float*)d_in[1];
    const float* beta  = (const float*)d_in[2];
    const float* Wq    = (const float*)d_in[3];
    const float* Wk    = (const float*)d_in[4];
    const float* Wv    = (const float*)d_in[5];
    const float* Wg    = (const float*)d_in[6];
    const float* bg    = (const float*)d_in[7];
    const float* Wo    = (const float*)d_in[8];
    const float* bo    = (const float*)d_in[9];
    float* out = (float*)d_out;

    float *x, *q, *k, *v, *g, *o;
    cudaGetSymbolAddress((void**)&x, g_x);
    cudaGetSymbolAddress((void**)&q, g_q);
    cudaGetSymbolAddress((void**)&k, g_k);
    cudaGetSymbolAddress((void**)&v, g_v);
    cudaGetSymbolAddress((void**)&g, g_g);
    cudaGetSymbolAddress((void**)&o, g_o);

    cudaFuncSetAttribute(attn_kernel, cudaFuncAttributeMaxDynamicSharedMemorySize,
                         ATTN_SMEM_BYTES);

    // 1) layernorm
    ln_kernel<<<NL, 64>>>(m, gamma, beta);

    // 2) projections (q, k, v plain; g with sigmoid+bias)
    dim3 ggrid(256 / BN, NL / BM);
    gemm_kernel<<<ggrid, 256>>>(x, Wq, nullptr, q, 0);
    gemm_kernel<<<ggrid, 256>>>(x, Wk, nullptr, k, 0);
    gemm_kernel<<<ggrid, 256>>>(x, Wv, nullptr, v, 0);
    gemm_kernel<<<ggrid, 256>>>(x, Wg, bg,      g, 1);

    // 3) attention per (l, h)
    attn_kernel<<<LRES * NHEAD, 256, ATTN_SMEM_BYTES>>>();

    // 4) output projection + bias
    gemm_kernel<<<ggrid, 256>>>(o, Wo, bo, out, 2);
}

// round 8
// speedup vs baseline: 1.7255x; 1.7255x over previous
#include <cuda_runtime.h>
#include <math.h>

#define NSEQ  256
#define LRES  384
#define MDIM  256
#define NHEAD 8
#define CDIM  32
#define HC    256
#define NL    (NSEQ * LRES)            // 98304
#define SQC   0.17677669529663687f     // 1/sqrt(32)

typedef unsigned long long ull;

// -------- scratch (static device globals; no allocations allowed) --------
__device__ float g_x[(size_t)NL * MDIM];   // layernormed input
__device__ float g_q[(size_t)NL * HC];
__device__ float g_k[(size_t)NL * HC];
__device__ float g_v[(size_t)NL * HC];
__device__ float g_g[(size_t)NL * HC];     // sigmoid gate (activation applied)
__device__ float g_o[(size_t)NL * HC];     // gated attention output

// -------- f32x2 helpers (B300: FFMA2 reachable only via PTX) --------
__device__ __forceinline__ void fma2(ull& d, ull a, ull b) {
    asm("fma.rn.f32x2 %0, %1, %2, %0;" : "+l"(d) : "l"(a), "l"(b));
}
__device__ __forceinline__ ull dup2(float a) {
    ull r;
    asm("mov.b64 %0, {%1, %1};" : "=l"(r) : "f"(a));
    return r;
}
__device__ __forceinline__ float2 unpk(ull v) {
    float2 f;
    asm("mov.b64 {%0, %1}, %2;" : "=f"(f.x), "=f"(f.y) : "l"(v));
    return f;
}

// ============================ LayerNorm ============================
__global__ void ln_kernel(const float* __restrict__ m,
                          const float* __restrict__ gamma,
                          const float* __restrict__ beta) {
    int row = blockIdx.x;
    const float4* mr = (const float4*)(m + (size_t)row * MDIM);
    float4* xr = (float4*)(g_x + (size_t)row * MDIM);
    int tid = threadIdx.x;

    float4 v = mr[tid];
    float s  = v.x + v.y + v.z + v.w;
    float ss = v.x * v.x + v.y * v.y + v.z * v.z + v.w * v.w;
    #pragma unroll
    for (int o = 16; o; o >>= 1) {
        s  += __shfl_xor_sync(0xffffffffu, s,  o);
        ss += __shfl_xor_sync(0xffffffffu, ss, o);
    }
    __shared__ float sh[4];
    if ((tid & 31) == 0) { sh[tid >> 5] = s; sh[2 + (tid >> 5)] = ss; }
    __syncthreads();
    s  = sh[0] + sh[1];
    ss = sh[2] + sh[3];
    float mu  = s * (1.0f / MDIM);
    float var = ss * (1.0f / MDIM) - mu * mu;
    float inv = rsqrtf(var + 1e-5f);

    float4 gm = ((const float4*)gamma)[tid];
    float4 bt = ((const float4*)beta)[tid];
    float4 r;
    r.x = (v.x - mu) * inv * gm.x + bt.x;
    r.y = (v.y - mu) * inv * gm.y + bt.y;
    r.z = (v.z - mu) * inv * gm.z + bt.z;
    r.w = (v.w - mu) * inv * gm.w + bt.w;
    xr[tid] = r;
}

// ============================ GEMM (FFMA2) ============================
// C[M,256] = A[M,256] * B[256,256]; 128x128x16 tiles, 8x8 microtile.
// epi_mode: 0 plain, 1 sigmoid(v + bias), 2 v + bias
#define BM 128
#define BN 128
#define BK 16

__global__ __launch_bounds__(256, 2)
void gemm_kernel(const float* __restrict__ A,
                 const float* __restrict__ B,
                 const float* __restrict__ bias,
                 float* __restrict__ Cout,
                 int epi_mode) {
    __shared__ float As[BK][BM];   // [k][m] (transposed A tile)
    __shared__ float Bs[BK][BN];   // [k][n]

    int bn = blockIdx.x * BN;
    int bm = blockIdx.y * BM;
    int tid = threadIdx.x;                 // 256 threads
    int tx = tid & 15, ty = tid >> 4;

    // tile loaders: A: 128 rows x 16 k -> 8 floats/thread; B: 16 k x 128 n
    int ar = tid >> 1;                     // 0..127
    int ac = (tid & 1) * 8;                // 0 or 8
    int br = tid >> 4;                     // 0..15
    int bc = (tid & 15) * 8;               // 0..120

    const float* Aptr = A + (size_t)(bm + ar) * 256 + ac;
    const float* Bptr = B + (size_t)br * 256 + bn + bc;

    ull acc[8][4];
    #pragma unroll
    for (int i = 0; i < 8; i++)
        #pragma unroll
        for (int j = 0; j < 4; j++) acc[i][j] = 0ULL;

    // preload tile 0 into registers
    float4 pa0 = *(const float4*)(Aptr);
    float4 pa1 = *(const float4*)(Aptr + 4);
    float4 pb0 = *(const float4*)(Bptr);
    float4 pb1 = *(const float4*)(Bptr + 4);

    for (int k0 = 0; k0 < 256; k0 += BK) {
        // store current tile
        As[ac + 0][ar] = pa0.x; As[ac + 1][ar] = pa0.y;
        As[ac + 2][ar] = pa0.z; As[ac + 3][ar] = pa0.w;
        As[ac + 4][ar] = pa1.x; As[ac + 5][ar] = pa1.y;
        As[ac + 6][ar] = pa1.z; As[ac + 7][ar] = pa1.w;
        *(float4*)&Bs[br][bc]     = pb0;
        *(float4*)&Bs[br][bc + 4] = pb1;
        __syncthreads();

        // prefetch next tile
        if (k0 + BK < 256) {
            pa0 = *(const float4*)(Aptr + k0 + BK);
            pa1 = *(const float4*)(Aptr + k0 + BK + 4);
            pb0 = *(const float4*)(Bptr + (size_t)(k0 + BK) * 256);
            pb1 = *(const float4*)(Bptr + (size_t)(k0 + BK) * 256 + 4);
        }

        #pragma unroll
        for (int kk = 0; kk < BK; kk++) {
            float4 alo = *(float4*)&As[kk][ty * 4];
            float4 ahi = *(float4*)&As[kk][64 + ty * 4];
            ulonglong2 bd0 = *(ulonglong2*)&Bs[kk][tx * 4];
            ulonglong2 bd1 = *(ulonglong2*)&Bs[kk][64 + tx * 4];
            ull b2[4] = { bd0.x, bd0.y, bd1.x, bd1.y };
            float av[8] = { alo.x, alo.y, alo.z, alo.w,
                            ahi.x, ahi.y, ahi.z, ahi.w };
            ull a2[8];
            #pragma unroll
            for (int i = 0; i < 8; i++) a2[i] = dup2(av[i]);
            #pragma unroll
            for (int i = 0; i < 8; i++)
                #pragma unroll
                for (int jp = 0; jp < 4; jp++)
                    fma2(acc[i][jp], a2[i], b2[jp]);
        }
        __syncthreads();
    }

    // epilogue
    float4 bia0 = make_float4(0.f, 0.f, 0.f, 0.f), bia1 = bia0;
    if (epi_mode != 0) {
        bia0 = *(const float4*)&bias[bn + tx * 4];
        bia1 = *(const float4*)&bias[bn + 64 + tx * 4];
    }
    #pragma unroll
    for (int half = 0; half < 2; half++) {
        #pragma unroll
        for (int i = 0; i < 4; i++) {
            int row = bm + half * 64 + ty * 4 + i;
            int ii = half * 4 + i;
            float2 c0 = unpk(acc[ii][0]);
            float2 c1 = unpk(acc[ii][1]);
            float2 c2 = unpk(acc[ii][2]);
            float2 c3 = unpk(acc[ii][3]);
            float v0[8] = { c0.x, c0.y, c1.x, c1.y, c2.x, c2.y, c3.x, c3.y };
            float bb[8] = { bia0.x, bia0.y, bia0.z, bia0.w,
                            bia1.x, bia1.y, bia1.z, bia1.w };
            if (epi_mode == 1) {
                #pragma unroll
                for (int j = 0; j < 8; j++)
                    v0[j] = 1.0f / (1.0f + __expf(-(v0[j] + bb[j])));
            } else if (epi_mode == 2) {
                #pragma unroll
                for (int j = 0; j < 8; j++) v0[j] += bb[j];
            }
            *(float4*)&Cout[(size_t)row * 256 + bn + tx * 4] =
                make_float4(v0[0], v0[1], v0[2], v0[3]);
            *(float4*)&Cout[(size_t)row * 256 + bn + 64 + tx * 4] =
                make_float4(v0[4], v0[5], v0[6], v0[7]);
        }
    }
}

// ============================ Attention ============================
// one CTA (256 threads = 8 warps) per (l, h). 4 query rows per warp.
#define KST 36        // k_sm row stride (floats)
#define VST 260       // v^T row stride
#define PST 260       // softmax prob stride (per s-row)

#define K_SM_F  (256 * KST)                       // 9216
#define V_SM_F  (32 * VST)                        // 8320
#define P_SM_F  (32 * PST)                        // 8320 (32 rows in flight)
#define Q_SM_F  (32 * 32)                         // 1024
#define ATTN_SMEM_BYTES ((K_SM_F + V_SM_F + P_SM_F + Q_SM_F) * 4)   // 107520

__global__ __launch_bounds__(256, 2) void attn_kernel() {
    extern __shared__ float sm[];
    float* k_sm = sm;
    float* v_sm = sm + K_SM_F;
    float* p_sm = sm + K_SM_F + V_SM_F;
    float* q_sm = sm + K_SM_F + V_SM_F + P_SM_F;

    int l = blockIdx.x >> 3;
    int h = blockIdx.x & 7;
    int tid = threadIdx.x;
    int w = tid >> 5, lane = tid & 31;

    size_t head_off = (size_t)h * CDIM;

    // load K (256 x 32) and V^T (32 x 256) into smem
    for (int idx = tid; idx < 256 * 32; idx += 256) {
        int t = idx >> 5, c = idx & 31;
        size_t gi = ((size_t)(t * LRES + l)) * HC + head_off + c;
        k_sm[t * KST + c] = g_k[gi];
        v_sm[c * VST + t] = g_v[gi];
    }
    __syncthreads();

    // each warp owns 4 query rows per iteration: s = it*32 + w*4 + r
    for (int it = 0; it < 8; it++) {
        int s0 = it * 32 + w * 4;
        int prow = w * 4;                  // this warp's p_sm / q_sm row base

        #pragma unroll
        for (int r = 0; r < 4; r++) {
            size_t qi = ((size_t)((s0 + r) * LRES + l)) * HC + head_off + lane;
            q_sm[(prow + r) * 32 + lane] = g_q[qi];
        }
        __syncwarp();

        // ---- scores: sc2[i][r] packs (even-c, odd-c) partial dots ----
        ull sc2[8][4];
        #pragma unroll
        for (int i = 0; i < 8; i++)
            #pragma unroll
            for (int r = 0; r < 4; r++) sc2[i][r] = 0ULL;

        #pragma unroll
        for (int cb = 0; cb < 4; cb++) {   // 8 channels = 4 pairs per block
            ull q2[4][4];
            #pragma unroll
            for (int r = 0; r < 4; r++) {
                ulonglong2 t0 = *(ulonglong2*)&q_sm[(prow + r) * 32 + cb * 8];
                ulonglong2 t1 = *(ulonglong2*)&q_sm[(prow + r) * 32 + cb * 8 + 4];
                q2[r][0] = t0.x; q2[r][1] = t0.y; q2[r][2] = t1.x; q2[r][3] = t1.y;
            }
            #pragma unroll
            for (int i = 0; i < 8; i++) {
                int t = i * 32 + lane;
                ulonglong2 k0 = *(ulonglong2*)&k_sm[t * KST + cb * 8];
                ulonglong2 k1 = *(ulonglong2*)&k_sm[t * KST + cb * 8 + 4];
                ull k2[4] = { k0.x, k0.y, k1.x, k1.y };
                #pragma unroll
                for (int r = 0; r < 4; r++) {
                    fma2(sc2[i][r], k2[0], q2[r][0]);
                    fma2(sc2[i][r], k2[1], q2[r][1]);
                    fma2(sc2[i][r], k2[2], q2[r][2]);
                    fma2(sc2[i][r], k2[3], q2[r][3]);
                }
            }
        }

        // horizontal add + scale
        float sc[8][4];
        #pragma unroll
        for (int i = 0; i < 8; i++)
            #pragma unroll
            for (int r = 0; r < 4; r++) {
                float2 f = unpk(sc2[i][r]);
                sc[i][r] = (f.x + f.y) * SQC;
            }

        // ---- softmax per row r over 256 t (8 per lane) ----
        #pragma unroll
        for (int r = 0; r < 4; r++) {
            float mx = sc[0][r];
            #pragma unroll
            for (int i = 1; i < 8; i++) mx = fmaxf(mx, sc[i][r]);
            #pragma unroll
            for (int o = 16; o; o >>= 1)
                mx = fmaxf(mx, __shfl_xor_sync(0xffffffffu, mx, o));
            float sum = 0.0f;
            #pragma unroll
            for (int i = 0; i < 8; i++) {
                sc[i][r] = __expf(sc[i][r] - mx);
                sum += sc[i][r];
            }
            #pragma unroll
            for (int o = 16; o; o >>= 1)
                sum += __shfl_xor_sync(0xffffffffu, sum, o);
            float rinv = 1.0f / sum;
            #pragma unroll
            for (int i = 0; i < 8; i++)
                p_sm[(prow + r) * PST + i * 32 + lane] = sc[i][r] * rinv;
        }
        __syncwarp();

        // ---- output: o[r][c=lane] = sum_t p[r][t] * v[t][c], packed over t ----
        ull oa[4] = { 0ULL, 0ULL, 0ULL, 0ULL };
        #pragma unroll
        for (int tq = 0; tq < 32; tq++) {  // 8 t's = 4 packed pairs
            ulonglong2 v0 = *(ulonglong2*)&v_sm[lane * VST + tq * 8];
            ulonglong2 v1 = *(ulonglong2*)&v_sm[lane * VST + tq * 8 + 4];
            ull v2[4] = { v0.x, v0.y, v1.x, v1.y };
            #pragma unroll
            for (int r = 0; r < 4; r++) {
                ulonglong2 p0 = *(ulonglong2*)&p_sm[(prow + r) * PST + tq * 8];
                ulonglong2 p1 = *(ulonglong2*)&p_sm[(prow + r) * PST + tq * 8 + 4];
                fma2(oa[r], v2[0], p0.x);
                fma2(oa[r], v2[1], p0.y);
                fma2(oa[r], v2[2], p1.x);
                fma2(oa[r], v2[3], p1.y);
            }
        }

        #pragma unroll
        for (int r = 0; r < 4; r++) {
            float2 f = unpk(oa[r]);
            float ov = f.x + f.y;
            size_t qi = ((size_t)((s0 + r) * LRES + l)) * HC + head_off + lane;
            g_o[qi] = ov * g_g[qi];
        }
        __syncwarp();
    }
}

// ============================ launch ============================
extern "C" void kernel_launch(void* const* d_in, const int* in_sizes, int n_in,
                              void* d_out, int out_size) {
    (void)in_sizes; (void)n_in; (void)out_size;
    const float* m     = (const float*)d_in[0];
    const float* gamma = (const float*)d_in[1];
    const float* beta  = (const float*)d_in[2];
    const float* Wq    = (const float*)d_in[3];
    const float* Wk    = (const float*)d_in[4];
    const float* Wv    = (const float*)d_in[5];
    const float* Wg    = (const float*)d_in[6];
    const float* bg    = (const float*)d_in[7];
    const float* Wo    = (const float*)d_in[8];
    const float* bo    = (const float*)d_in[9];
    float* out = (float*)d_out;

    float *x, *q, *k, *v, *g, *o;
    cudaGetSymbolAddress((void**)&x, g_x);
    cudaGetSymbolAddress((void**)&q, g_q);
    cudaGetSymbolAddress((void**)&k, g_k);
    cudaGetSymbolAddress((void**)&v, g_v);
    cudaGetSymbolAddress((void**)&g, g_g);
    cudaGetSymbolAddress((void**)&o, g_o);

    cudaFuncSetAttribute(attn_kernel, cudaFuncAttributeMaxDynamicSharedMemorySize,
                         ATTN_SMEM_BYTES);

    // 1) layernorm
    ln_kernel<<<NL, 64>>>(m, gamma, beta);

    // 2) projections (q, k, v plain; g with sigmoid+bias)
    dim3 ggrid(256 / BN, NL / BM);
    gemm_kernel<<<ggrid, 256>>>(x, Wq, nullptr, q, 0);
    gemm_kernel<<<ggrid, 256>>>(x, Wk, nullptr, k, 0);
    gemm_kernel<<<ggrid, 256>>>(x, Wv, nullptr, v, 0);
    gemm_kernel<<<ggrid, 256>>>(x, Wg, bg,      g, 1);

    // 3) attention per (l, h)
    attn_kernel<<<LRES * NHEAD, 256, ATTN_SMEM_BYTES>>>();

    // 4) output projection + bias
    gemm_kernel<<<ggrid, 256>>>(o, Wo, bo, out, 2);
}

// round 9
// speedup vs baseline: 1.7256x; 1.0001x over previous
#include <cuda_runtime.h>
#include <math.h>

#define NSEQ  256
#define LRES  384
#define MDIM  256
#define NHEAD 8
#define CDIM  32
#define HC    256
#define NL    (NSEQ * LRES)            // 98304
#define SQC   0.17677669529663687f     // 1/sqrt(32)

typedef unsigned long long ull;

// -------- scratch (static device globals; no allocations allowed) --------
__device__ float g_x[(size_t)NL * MDIM];   // layernormed input
__device__ float g_q[(size_t)NL * HC];
__device__ float g_k[(size_t)NL * HC];
__device__ float g_v[(size_t)NL * HC];
__device__ float g_g[(size_t)NL * HC];     // sigmoid gate (activation applied)
__device__ float g_o[(size_t)NL * HC];     // gated attention output

// -------- f32x2 helpers (B300: FFMA2 reachable only via PTX) --------
__device__ __forceinline__ void fma2(ull& d, ull a, ull b) {
    asm("fma.rn.f32x2 %0, %1, %2, %0;" : "+l"(d) : "l"(a), "l"(b));
}
__device__ __forceinline__ ull dup2(float a) {
    ull r;
    asm("mov.b64 %0, {%1, %1};" : "=l"(r) : "f"(a));
    return r;
}
__device__ __forceinline__ float2 unpk(ull v) {
    float2 f;
    asm("mov.b64 {%0, %1}, %2;" : "=f"(f.x), "=f"(f.y) : "l"(v));
    return f;
}

// ============================ LayerNorm ============================
__global__ void ln_kernel(const float* __restrict__ m,
                          const float* __restrict__ gamma,
                          const float* __restrict__ beta) {
    int row = blockIdx.x;
    const float4* mr = (const float4*)(m + (size_t)row * MDIM);
    float4* xr = (float4*)(g_x + (size_t)row * MDIM);
    int tid = threadIdx.x;

    float4 v = mr[tid];
    float s  = v.x + v.y + v.z + v.w;
    float ss = v.x * v.x + v.y * v.y + v.z * v.z + v.w * v.w;
    #pragma unroll
    for (int o = 16; o; o >>= 1) {
        s  += __shfl_xor_sync(0xffffffffu, s,  o);
        ss += __shfl_xor_sync(0xffffffffu, ss, o);
    }
    __shared__ float sh[4];
    if ((tid & 31) == 0) { sh[tid >> 5] = s; sh[2 + (tid >> 5)] = ss; }
    __syncthreads();
    s  = sh[0] + sh[1];
    ss = sh[2] + sh[3];
    float mu  = s * (1.0f / MDIM);
    float var = ss * (1.0f / MDIM) - mu * mu;
    float inv = rsqrtf(var + 1e-5f);

    float4 gm = ((const float4*)gamma)[tid];
    float4 bt = ((const float4*)beta)[tid];
    float4 r;
    r.x = (v.x - mu) * inv * gm.x + bt.x;
    r.y = (v.y - mu) * inv * gm.y + bt.y;
    r.z = (v.z - mu) * inv * gm.z + bt.z;
    r.w = (v.w - mu) * inv * gm.w + bt.w;
    xr[tid] = r;
}

// ============================ GEMM (FFMA2) ============================
// C[M,256] = A[M,256] * B[256,256]; 128x128x16 tiles, 8x8 microtile.
// epi_mode: 0 plain, 1 sigmoid(v + bias), 2 v + bias
#define BM 128
#define BN 128
#define BK 16

__global__ __launch_bounds__(256, 2)
void gemm_kernel(const float* __restrict__ A,
                 const float* __restrict__ B,
                 const float* __restrict__ bias,
                 float* __restrict__ Cout,
                 int epi_mode) {
    __shared__ float As[BK][BM];   // [k][m] (transposed A tile)
    __shared__ float Bs[BK][BN];   // [k][n]

    int bn = blockIdx.x * BN;
    int bm = blockIdx.y * BM;
    int tid = threadIdx.x;                 // 256 threads
    int tx = tid & 15, ty = tid >> 4;

    // tile loaders: A: 128 rows x 16 k -> 8 floats/thread; B: 16 k x 128 n
    int ar = tid >> 1;                     // 0..127
    int ac = (tid & 1) * 8;                // 0 or 8
    int br = tid >> 4;                     // 0..15
    int bc = (tid & 15) * 8;               // 0..120

    const float* Aptr = A + (size_t)(bm + ar) * 256 + ac;
    const float* Bptr = B + (size_t)br * 256 + bn + bc;

    ull acc[8][4];
    #pragma unroll
    for (int i = 0; i < 8; i++)
        #pragma unroll
        for (int j = 0; j < 4; j++) acc[i][j] = 0ULL;

    // preload tile 0 into registers
    float4 pa0 = *(const float4*)(Aptr);
    float4 pa1 = *(const float4*)(Aptr + 4);
    float4 pb0 = *(const float4*)(Bptr);
    float4 pb1 = *(const float4*)(Bptr + 4);

    for (int k0 = 0; k0 < 256; k0 += BK) {
        // store current tile
        As[ac + 0][ar] = pa0.x; As[ac + 1][ar] = pa0.y;
        As[ac + 2][ar] = pa0.z; As[ac + 3][ar] = pa0.w;
        As[ac + 4][ar] = pa1.x; As[ac + 5][ar] = pa1.y;
        As[ac + 6][ar] = pa1.z; As[ac + 7][ar] = pa1.w;
        *(float4*)&Bs[br][bc]     = pb0;
        *(float4*)&Bs[br][bc + 4] = pb1;
        __syncthreads();

        // prefetch next tile
        if (k0 + BK < 256) {
            pa0 = *(const float4*)(Aptr + k0 + BK);
            pa1 = *(const float4*)(Aptr + k0 + BK + 4);
            pb0 = *(const float4*)(Bptr + (size_t)(k0 + BK) * 256);
            pb1 = *(const float4*)(Bptr + (size_t)(k0 + BK) * 256 + 4);
        }

        #pragma unroll
        for (int kk = 0; kk < BK; kk++) {
            float4 alo = *(float4*)&As[kk][ty * 4];
            float4 ahi = *(float4*)&As[kk][64 + ty * 4];
            ulonglong2 bd0 = *(ulonglong2*)&Bs[kk][tx * 4];
            ulonglong2 bd1 = *(ulonglong2*)&Bs[kk][64 + tx * 4];
            ull b2[4] = { bd0.x, bd0.y, bd1.x, bd1.y };
            float av[8] = { alo.x, alo.y, alo.z, alo.w,
                            ahi.x, ahi.y, ahi.z, ahi.w };
            ull a2[8];
            #pragma unroll
            for (int i = 0; i < 8; i++) a2[i] = dup2(av[i]);
            #pragma unroll
            for (int i = 0; i < 8; i++)
                #pragma unroll
                for (int jp = 0; jp < 4; jp++)
                    fma2(acc[i][jp], a2[i], b2[jp]);
        }
        __syncthreads();
    }

    // epilogue
    float4 bia0 = make_float4(0.f, 0.f, 0.f, 0.f), bia1 = bia0;
    if (epi_mode != 0) {
        bia0 = *(const float4*)&bias[bn + tx * 4];
        bia1 = *(const float4*)&bias[bn + 64 + tx * 4];
    }
    #pragma unroll
    for (int half = 0; half < 2; half++) {
        #pragma unroll
        for (int i = 0; i < 4; i++) {
            int row = bm + half * 64 + ty * 4 + i;
            int ii = half * 4 + i;
            float2 c0 = unpk(acc[ii][0]);
            float2 c1 = unpk(acc[ii][1]);
            float2 c2 = unpk(acc[ii][2]);
            float2 c3 = unpk(acc[ii][3]);
            float v0[8] = { c0.x, c0.y, c1.x, c1.y, c2.x, c2.y, c3.x, c3.y };
            float bb[8] = { bia0.x, bia0.y, bia0.z, bia0.w,
                            bia1.x, bia1.y, bia1.z, bia1.w };
            if (epi_mode == 1) {
                #pragma unroll
                for (int j = 0; j < 8; j++)
                    v0[j] = 1.0f / (1.0f + __expf(-(v0[j] + bb[j])));
            } else if (epi_mode == 2) {
                #pragma unroll
                for (int j = 0; j < 8; j++) v0[j] += bb[j];
            }
            *(float4*)&Cout[(size_t)row * 256 + bn + tx * 4] =
                make_float4(v0[0], v0[1], v0[2], v0[3]);
            *(float4*)&Cout[(size_t)row * 256 + bn + 64 + tx * 4] =
                make_float4(v0[4], v0[5], v0[6], v0[7]);
        }
    }
}

// ============================ Attention ============================
// one CTA (256 threads = 8 warps) per (l, h). 4 query rows per warp.
#define KST 36        // k_sm row stride (floats)
#define VST 260       // v^T row stride
#define PST 260       // softmax prob stride (per s-row)

#define K_SM_F  (256 * KST)                       // 9216
#define V_SM_F  (32 * VST)                        // 8320
#define P_SM_F  (32 * PST)                        // 8320 (32 rows in flight)
#define Q_SM_F  (32 * 32)                         // 1024
#define ATTN_SMEM_BYTES ((K_SM_F + V_SM_F + P_SM_F + Q_SM_F) * 4)   // 107520

__global__ __launch_bounds__(256, 2) void attn_kernel() {
    extern __shared__ float sm[];
    float* k_sm = sm;
    float* v_sm = sm + K_SM_F;
    float* p_sm = sm + K_SM_F + V_SM_F;
    float* q_sm = sm + K_SM_F + V_SM_F + P_SM_F;

    int l = blockIdx.x >> 3;
    int h = blockIdx.x & 7;
    int tid = threadIdx.x;
    int w = tid >> 5, lane = tid & 31;

    size_t head_off = (size_t)h * CDIM;

    // load K (256 x 32) and V^T (32 x 256) into smem
    for (int idx = tid; idx < 256 * 32; idx += 256) {
        int t = idx >> 5, c = idx & 31;
        size_t gi = ((size_t)(t * LRES + l)) * HC + head_off + c;
        k_sm[t * KST + c] = g_k[gi];
        v_sm[c * VST + t] = g_v[gi];
    }
    __syncthreads();

    // each warp owns 4 query rows per iteration: s = it*32 + w*4 + r
    for (int it = 0; it < 8; it++) {
        int s0 = it * 32 + w * 4;
        int prow = w * 4;                  // this warp's p_sm / q_sm row base

        #pragma unroll
        for (int r = 0; r < 4; r++) {
            size_t qi = ((size_t)((s0 + r) * LRES + l)) * HC + head_off + lane;
            q_sm[(prow + r) * 32 + lane] = g_q[qi];
        }
        __syncwarp();

        // ---- scores: sc2[i][r] packs (even-c, odd-c) partial dots ----
        ull sc2[8][4];
        #pragma unroll
        for (int i = 0; i < 8; i++)
            #pragma unroll
            for (int r = 0; r < 4; r++) sc2[i][r] = 0ULL;

        #pragma unroll
        for (int cb = 0; cb < 4; cb++) {   // 8 channels = 4 pairs per block
            ull q2[4][4];
            #pragma unroll
            for (int r = 0; r < 4; r++) {
                ulonglong2 t0 = *(ulonglong2*)&q_sm[(prow + r) * 32 + cb * 8];
                ulonglong2 t1 = *(ulonglong2*)&q_sm[(prow + r) * 32 + cb * 8 + 4];
                q2[r][0] = t0.x; q2[r][1] = t0.y; q2[r][2] = t1.x; q2[r][3] = t1.y;
            }
            #pragma unroll
            for (int i = 0; i < 8; i++) {
                int t = i * 32 + lane;
                ulonglong2 k0 = *(ulonglong2*)&k_sm[t * KST + cb * 8];
                ulonglong2 k1 = *(ulonglong2*)&k_sm[t * KST + cb * 8 + 4];
                ull k2[4] = { k0.x, k0.y, k1.x, k1.y };
                #pragma unroll
                for (int r = 0; r < 4; r++) {
                    fma2(sc2[i][r], k2[0], q2[r][0]);
                    fma2(sc2[i][r], k2[1], q2[r][1]);
                    fma2(sc2[i][r], k2[2], q2[r][2]);
                    fma2(sc2[i][r], k2[3], q2[r][3]);
                }
            }
        }

        // horizontal add + scale
        float sc[8][4];
        #pragma unroll
        for (int i = 0; i < 8; i++)
            #pragma unroll
            for (int r = 0; r < 4; r++) {
                float2 f = unpk(sc2[i][r]);
                sc[i][r] = (f.x + f.y) * SQC;
            }

        // ---- softmax per row r over 256 t (8 per lane) ----
        #pragma unroll
        for (int r = 0; r < 4; r++) {
            float mx = sc[0][r];
            #pragma unroll
            for (int i = 1; i < 8; i++) mx = fmaxf(mx, sc[i][r]);
            #pragma unroll
            for (int o = 16; o; o >>= 1)
                mx = fmaxf(mx, __shfl_xor_sync(0xffffffffu, mx, o));
            float sum = 0.0f;
            #pragma unroll
            for (int i = 0; i < 8; i++) {
                sc[i][r] = __expf(sc[i][r] - mx);
                sum += sc[i][r];
            }
            #pragma unroll
            for (int o = 16; o; o >>= 1)
                sum += __shfl_xor_sync(0xffffffffu, sum, o);
            float rinv = 1.0f / sum;
            #pragma unroll
            for (int i = 0; i < 8; i++)
                p_sm[(prow + r) * PST + i * 32 + lane] = sc[i][r] * rinv;
        }
        __syncwarp();

        // ---- output: o[r][c=lane] = sum_t p[r][t] * v[t][c], packed over t ----
        ull oa[4] = { 0ULL, 0ULL, 0ULL, 0ULL };
        #pragma unroll
        for (int tq = 0; tq < 32; tq++) {  // 8 t's = 4 packed pairs
            ulonglong2 v0 = *(ulonglong2*)&v_sm[lane * VST + tq * 8];
            ulonglong2 v1 = *(ulonglong2*)&v_sm[lane * VST + tq * 8 + 4];
            ull v2[4] = { v0.x, v0.y, v1.x, v1.y };
            #pragma unroll
            for (int r = 0; r < 4; r++) {
                ulonglong2 p0 = *(ulonglong2*)&p_sm[(prow + r) * PST + tq * 8];
                ulonglong2 p1 = *(ulonglong2*)&p_sm[(prow + r) * PST + tq * 8 + 4];
                fma2(oa[r], v2[0], p0.x);
                fma2(oa[r], v2[1], p0.y);
                fma2(oa[r], v2[2], p1.x);
                fma2(oa[r], v2[3], p1.y);
            }
        }

        #pragma unroll
        for (int r = 0; r < 4; r++) {
            float2 f = unpk(oa[r]);
            float ov = f.x + f.y;
            size_t qi = ((size_t)((s0 + r) * LRES + l)) * HC + head_off + lane;
            g_o[qi] = ov * g_g[qi];
        }
        __syncwarp();
    }
}

// ============================ launch ============================
extern "C" void kernel_launch(void* const* d_in, const int* in_sizes, int n_in,
                              void* d_out, int out_size) {
    (void)in_sizes; (void)n_in; (void)out_size;
    const float* m     = (const float*)d_in[0];
    const float* gamma = (const float*)d_in[1];
    const float* beta  = (const float*)d_in[2];
    const float* Wq    = (const float*)d_in[3];
    const float* Wk    = (const float*)d_in[4];
    const float* Wv    = (const float*)d_in[5];
    const float* Wg    = (const float*)d_in[6];
    const float* bg    = (const float*)d_in[7];
    const float* Wo    = (const float*)d_in[8];
    const float* bo    = (const float*)d_in[9];
    float* out = (float*)d_out;

    float *x, *q, *k, *v, *g, *o;
    cudaGetSymbolAddress((void**)&x, g_x);
    cudaGetSymbolAddress((void**)&q, g_q);
    cudaGetSymbolAddress((void**)&k, g_k);
    cudaGetSymbolAddress((void**)&v, g_v);
    cudaGetSymbolAddress((void**)&g, g_g);
    cudaGetSymbolAddress((void**)&o, g_o);

    cudaFuncSetAttribute(attn_kernel, cudaFuncAttributeMaxDynamicSharedMemorySize,
                         ATTN_SMEM_BYTES);

    // 1) layernorm
    ln_kernel<<<NL, 64>>>(m, gamma, beta);

    // 2) projections (q, k, v plain; g with sigmoid+bias)
    dim3 ggrid(256 / BN, NL / BM);
    gemm_kernel<<<ggrid, 256>>>(x, Wq, nullptr, q, 0);
    gemm_kernel<<<ggrid, 256>>>(x, Wk, nullptr, k, 0);
    gemm_kernel<<<ggrid, 256>>>(x, Wv, nullptr, v, 0);
    gemm_kernel<<<ggrid, 256>>>(x, Wg, bg,      g, 1);

    // 3) attention per (l, h)
    attn_kernel<<<LRES * NHEAD, 256, ATTN_SMEM_BYTES>>>();

    // 4) output projection + bias
    gemm_kernel<<<ggrid, 256>>>(o, Wo, bo, out, 2);
}

// round 11
// speedup vs baseline: 2.3766x; 1.3773x over previous
#include <cuda_runtime.h>
#include <math.h>
#include <stdint.h>

#define NSEQ  256
#define LRES  384
#define MDIM  256
#define NHEAD 8
#define CDIM  32
#define HC    256
#define NL    (NSEQ * LRES)            // 98304
#define SQC   0.17677669529663687f     // 1/sqrt(32)

typedef unsigned long long ull;

// -------- scratch (static device globals; no allocations allowed) --------
__device__ float g_x[(size_t)NL * MDIM];   // layernormed input
__device__ float g_q[(size_t)NL * HC];
__device__ float g_k[(size_t)NL * HC];
__device__ float g_v[(size_t)NL * HC];
__device__ float g_g[(size_t)NL * HC];     // sigmoid gate (activation applied)
__device__ float g_o[(size_t)NL * HC];     // gated attention output
__device__ float g_wt[5 * 256 * 256];      // transposed weights [n][k]

// -------- f32x2 helpers --------
__device__ __forceinline__ void fma2(ull& d, ull a, ull b) {
    asm("fma.rn.f32x2 %0, %1, %2, %0;" : "+l"(d) : "l"(a), "l"(b));
}
__device__ __forceinline__ float2 unpk(ull v) {
    float2 f;
    asm("mov.b64 {%0, %1}, %2;" : "=f"(f.x), "=f"(f.y) : "l"(v));
    return f;
}

// -------- tf32 helpers (mma.sync path: no arch-suffix, works on compute_103) --------
__device__ __forceinline__ float tf32r(float f) {
    uint32_t u;
    asm("cvt.rna.tf32.f32 %0, %1;" : "=r"(u) : "f"(f));
    return __uint_as_float(u);
}
__device__ __forceinline__ void mma_16x8x8(float* c, const uint32_t* a, const uint32_t* b) {
    asm volatile(
        "mma.sync.aligned.m16n8k8.row.col.f32.tf32.tf32.f32 "
        "{%0,%1,%2,%3}, {%4,%5,%6,%7}, {%8,%9}, {%0,%1,%2,%3};"
        : "+f"(c[0]), "+f"(c[1]), "+f"(c[2]), "+f"(c[3])
        : "r"(a[0]), "r"(a[1]), "r"(a[2]), "r"(a[3]), "r"(b[0]), "r"(b[1]));
}

// ============================ LayerNorm ============================
__global__ void ln_kernel(const float* __restrict__ m,
                          const float* __restrict__ gamma,
                          const float* __restrict__ beta) {
    int row = blockIdx.x;
    const float4* mr = (const float4*)(m + (size_t)row * MDIM);
    float4* xr = (float4*)(g_x + (size_t)row * MDIM);
    int tid = threadIdx.x;

    float4 v = mr[tid];
    float s  = v.x + v.y + v.z + v.w;
    float ss = v.x * v.x + v.y * v.y + v.z * v.z + v.w * v.w;
    #pragma unroll
    for (int o = 16; o; o >>= 1) {
        s  += __shfl_xor_sync(0xffffffffu, s,  o);
        ss += __shfl_xor_sync(0xffffffffu, ss, o);
    }
    __shared__ float sh[4];
    if ((tid & 31) == 0) { sh[tid >> 5] = s; sh[2 + (tid >> 5)] = ss; }
    __syncthreads();
    s  = sh[0] + sh[1];
    ss = sh[2] + sh[3];
    float mu  = s * (1.0f / MDIM);
    float var = ss * (1.0f / MDIM) - mu * mu;
    float inv = rsqrtf(var + 1e-5f);

    float4 gm = ((const float4*)gamma)[tid];
    float4 bt = ((const float4*)beta)[tid];
    float4 r;
    r.x = (v.x - mu) * inv * gm.x + bt.x;
    r.y = (v.y - mu) * inv * gm.y + bt.y;
    r.z = (v.z - mu) * inv * gm.z + bt.z;
    r.w = (v.w - mu) * inv * gm.w + bt.w;
    xr[tid] = r;
}

// ============================ weight transpose ============================
__global__ void tr_kernel(const float* __restrict__ W, float* __restrict__ Wt) {
    __shared__ float t[32][33];
    int bx = blockIdx.x * 32, by = blockIdx.y * 32;
    int x = threadIdx.x, y = threadIdx.y;
    #pragma unroll
    for (int i = 0; i < 32; i += 8)
        t[y + i][x] = W[(size_t)(by + y + i) * 256 + bx + x];
    __syncthreads();
    #pragma unroll
    for (int i = 0; i < 32; i += 8)
        Wt[(size_t)(bx + y + i) * 256 + by + x] = t[x][y + i];
}

// ============================ tf32 mma.sync GEMM ============================
// C[M,256] = A[M,256] (row-major) * Bt[256 n][256 k] (K-major, pre-transposed).
// CTA: 512 threads (16 warps, 2x8), tile 128x256; warp-tile 64x32.
// K in 4 chunks of 64, smem stride 68 (conflict-free staging + frag loads).
// epi_mode: 0 plain, 1 sigmoid(v + bias), 2 v + bias
#define AS_ST 68
#define AS_F  (128 * AS_ST)            // 8704 floats
#define BS_F  (256 * AS_ST)            // 17408 floats
#define MMA_SMEM ((AS_F + BS_F) * 4)   // 104448 bytes

__global__ __launch_bounds__(512, 1)
void gemm_mma(const float* __restrict__ A,
              const float* __restrict__ Bt,
              const float* __restrict__ bias,
              float* __restrict__ Cout,
              int epi_mode) {
    extern __shared__ float sh[];
    float* As = sh;
    float* Bs = sh + AS_F;

    int tid = threadIdx.x;
    int wid = tid >> 5, lane = tid & 31;
    int gq = lane >> 2, tig = lane & 3;
    int wm = wid >> 3, wn = wid & 7;
    int bm = blockIdx.x * 128;

    float acc[4][4][4];
    #pragma unroll
    for (int i = 0; i < 4; i++)
        #pragma unroll
        for (int j = 0; j < 4; j++)
            #pragma unroll
            for (int z = 0; z < 4; z++) acc[i][j][z] = 0.0f;

    for (int kc = 0; kc < 4; kc++) {
        int k0g = kc * 64;
        // stage A chunk: 128 rows x 64 k (8192 floats, 4 float4/thread)
        #pragma unroll
        for (int j = 0; j < 4; j++) {
            int idx = j * 512 + tid;
            int r = idx >> 4, c = (idx & 15) << 2;
            float4 d = *(const float4*)&A[(size_t)(bm + r) * 256 + k0g + c];
            float4 t = make_float4(tf32r(d.x), tf32r(d.y), tf32r(d.z), tf32r(d.w));
            *(float4*)&As[r * AS_ST + c] = t;
        }
        // stage B chunk: 256 n-rows x 64 k (16384 floats, 8 float4/thread)
        #pragma unroll
        for (int j = 0; j < 8; j++) {
            int idx = j * 512 + tid;
            int n = idx >> 4, c = (idx & 15) << 2;
            float4 d = *(const float4*)&Bt[(size_t)n * 256 + k0g + c];
            float4 t = make_float4(tf32r(d.x), tf32r(d.y), tf32r(d.z), tf32r(d.w));
            *(float4*)&Bs[n * AS_ST + c] = t;
        }
        __syncthreads();

        #pragma unroll
        for (int kk = 0; kk < 8; kk++) {
            int k0 = kk * 8;
            uint32_t af[4][4], bf[4][2];
            #pragma unroll
            for (int mb = 0; mb < 4; mb++) {
                int r0 = wm * 64 + mb * 16 + gq;
                af[mb][0] = __float_as_uint(As[r0 * AS_ST + k0 + tig]);
                af[mb][1] = __float_as_uint(As[(r0 + 8) * AS_ST + k0 + tig]);
                af[mb][2] = __float_as_uint(As[r0 * AS_ST + k0 + tig + 4]);
                af[mb][3] = __float_as_uint(As[(r0 + 8) * AS_ST + k0 + tig + 4]);
            }
            #pragma unroll
            for (int nb = 0; nb < 4; nb++) {
                int n0 = wn * 32 + nb * 8 + gq;
                bf[nb][0] = __float_as_uint(Bs[n0 * AS_ST + k0 + tig]);
                bf[nb][1] = __float_as_uint(Bs[n0 * AS_ST + k0 + tig + 4]);
            }
            #pragma unroll
            for (int mb = 0; mb < 4; mb++)
                #pragma unroll
                for (int nb = 0; nb < 4; nb++)
                    mma_16x8x8(acc[mb][nb], af[mb], bf[nb]);
        }
        __syncthreads();
    }

    // epilogue: c0=(g,2t), c1=(g,2t+1), c2=(g+8,2t), c3=(g+8,2t+1)
    #pragma unroll
    for (int mb = 0; mb < 4; mb++) {
        int row = bm + wm * 64 + mb * 16 + gq;
        #pragma unroll
        for (int nb = 0; nb < 4; nb++) {
            int col = wn * 32 + nb * 8 + 2 * tig;
            float b0 = 0.f, b1 = 0.f;
            if (epi_mode != 0) { b0 = bias[col]; b1 = bias[col + 1]; }
            float v0 = acc[mb][nb][0], v1 = acc[mb][nb][1];
            float v2 = acc[mb][nb][2], v3 = acc[mb][nb][3];
            if (epi_mode == 1) {
                v0 = 1.0f / (1.0f + __expf(-(v0 + b0)));
                v1 = 1.0f / (1.0f + __expf(-(v1 + b1)));
                v2 = 1.0f / (1.0f + __expf(-(v2 + b0)));
                v3 = 1.0f / (1.0f + __expf(-(v3 + b1)));
            } else if (epi_mode == 2) {
                v0 += b0; v1 += b1; v2 += b0; v3 += b1;
            }
            *(float2*)&Cout[(size_t)row * 256 + col]       = make_float2(v0, v1);
            *(float2*)&Cout[(size_t)(row + 8) * 256 + col] = make_float2(v2, v3);
        }
    }
}

// ============================ Attention ============================
#define KST 36
#define VST 260
#define PST 260
#define K_SM_F  (256 * KST)
#define V_SM_F  (32 * VST)
#define P_SM_F  (32 * PST)
#define Q_SM_F  (32 * 32)
#define ATTN_SMEM_BYTES ((K_SM_F + V_SM_F + P_SM_F + Q_SM_F) * 4)   // 107520

__global__ __launch_bounds__(256, 2) void attn_kernel() {
    extern __shared__ float sm[];
    float* k_sm = sm;
    float* v_sm = sm + K_SM_F;
    float* p_sm = sm + K_SM_F + V_SM_F;
    float* q_sm = sm + K_SM_F + V_SM_F + P_SM_F;

    int l = blockIdx.x >> 3;
    int h = blockIdx.x & 7;
    int tid = threadIdx.x;
    int w = tid >> 5, lane = tid & 31;

    size_t head_off = (size_t)h * CDIM;

    for (int idx = tid; idx < 256 * 32; idx += 256) {
        int t = idx >> 5, c = idx & 31;
        size_t gi = ((size_t)(t * LRES + l)) * HC + head_off + c;
        k_sm[t * KST + c] = g_k[gi];
        v_sm[c * VST + t] = g_v[gi];
    }
    __syncthreads();

    for (int it = 0; it < 8; it++) {
        int s0 = it * 32 + w * 4;
        int prow = w * 4;

        #pragma unroll
        for (int r = 0; r < 4; r++) {
            size_t qi = ((size_t)((s0 + r) * LRES + l)) * HC + head_off + lane;
            q_sm[(prow + r) * 32 + lane] = g_q[qi];
        }
        __syncwarp();

        ull sc2[8][4];
        #pragma unroll
        for (int i = 0; i < 8; i++)
            #pragma unroll
            for (int r = 0; r < 4; r++) sc2[i][r] = 0ULL;

        #pragma unroll
        for (int cb = 0; cb < 4; cb++) {
            ull q2[4][4];
            #pragma unroll
            for (int r = 0; r < 4; r++) {
                ulonglong2 t0 = *(ulonglong2*)&q_sm[(prow + r) * 32 + cb * 8];
                ulonglong2 t1 = *(ulonglong2*)&q_sm[(prow + r) * 32 + cb * 8 + 4];
                q2[r][0] = t0.x; q2[r][1] = t0.y; q2[r][2] = t1.x; q2[r][3] = t1.y;
            }
            #pragma unroll
            for (int i = 0; i < 8; i++) {
                int t = i * 32 + lane;
                ulonglong2 k0 = *(ulonglong2*)&k_sm[t * KST + cb * 8];
                ulonglong2 k1 = *(ulonglong2*)&k_sm[t * KST + cb * 8 + 4];
                ull k2[4] = { k0.x, k0.y, k1.x, k1.y };
                #pragma unroll
                for (int r = 0; r < 4; r++) {
                    fma2(sc2[i][r], k2[0], q2[r][0]);
                    fma2(sc2[i][r], k2[1], q2[r][1]);
                    fma2(sc2[i][r], k2[2], q2[r][2]);
                    fma2(sc2[i][r], k2[3], q2[r][3]);
                }
            }
        }

        float sc[8][4];
        #pragma unroll
        for (int i = 0; i < 8; i++)
            #pragma unroll
            for (int r = 0; r < 4; r++) {
                float2 f = unpk(sc2[i][r]);
                sc[i][r] = (f.x + f.y) * SQC;
            }

        #pragma unroll
        for (int r = 0; r < 4; r++) {
            float mx = sc[0][r];
            #pragma unroll
            for (int i = 1; i < 8; i++) mx = fmaxf(mx, sc[i][r]);
            #pragma unroll
            for (int o = 16; o; o >>= 1)
                mx = fmaxf(mx, __shfl_xor_sync(0xffffffffu, mx, o));
            float sum = 0.0f;
            #pragma unroll
            for (int i = 0; i < 8; i++) {
                sc[i][r] = __expf(sc[i][r] - mx);
                sum += sc[i][r];
            }
            #pragma unroll
            for (int o = 16; o; o >>= 1)
                sum += __shfl_xor_sync(0xffffffffu, sum, o);
            float rinv = 1.0f / sum;
            #pragma unroll
            for (int i = 0; i < 8; i++)
                p_sm[(prow + r) * PST + i * 32 + lane] = sc[i][r] * rinv;
        }
        __syncwarp();

        ull oa[4] = { 0ULL, 0ULL, 0ULL, 0ULL };
        #pragma unroll
        for (int tq = 0; tq < 32; tq++) {
            ulonglong2 v0 = *(ulonglong2*)&v_sm[lane * VST + tq * 8];
            ulonglong2 v1 = *(ulonglong2*)&v_sm[lane * VST + tq * 8 + 4];
            ull v2[4] = { v0.x, v0.y, v1.x, v1.y };
            #pragma unroll
            for (int r = 0; r < 4; r++) {
                ulonglong2 p0 = *(ulonglong2*)&p_sm[(prow + r) * PST + tq * 8];
                ulonglong2 p1 = *(ulonglong2*)&p_sm[(prow + r) * PST + tq * 8 + 4];
                fma2(oa[r], v2[0], p0.x);
                fma2(oa[r], v2[1], p0.y);
                fma2(oa[r], v2[2], p1.x);
                fma2(oa[r], v2[3], p1.y);
            }
        }

        #pragma unroll
        for (int r = 0; r < 4; r++) {
            float2 f = unpk(oa[r]);
            float ov = f.x + f.y;
            size_t qi = ((size_t)((s0 + r) * LRES + l)) * HC + head_off + lane;
            g_o[qi] = ov * g_g[qi];
        }
        __syncwarp();
    }
}

// ============================ launch ============================
extern "C" void kernel_launch(void* const* d_in, const int* in_sizes, int n_in,
                              void* d_out, int out_size) {
    (void)in_sizes; (void)n_in; (void)out_size;
    const float* m     = (const float*)d_in[0];
    const float* gamma = (const float*)d_in[1];
    const float* beta  = (const float*)d_in[2];
    const float* Wq    = (const float*)d_in[3];
    const float* Wk    = (const float*)d_in[4];
    const float* Wv    = (const float*)d_in[5];
    const float* Wg    = (const float*)d_in[6];
    const float* bg    = (const float*)d_in[7];
    const float* Wo    = (const float*)d_in[8];
    const float* bo    = (const float*)d_in[9];
    float* out = (float*)d_out;

    float *x, *q, *k, *v, *g, *o, *wt;
    cudaGetSymbolAddress((void**)&x, g_x);
    cudaGetSymbolAddress((void**)&q, g_q);
    cudaGetSymbolAddress((void**)&k, g_k);
    cudaGetSymbolAddress((void**)&v, g_v);
    cudaGetSymbolAddress((void**)&g, g_g);
    cudaGetSymbolAddress((void**)&o, g_o);
    cudaGetSymbolAddress((void**)&wt, g_wt);

    cudaFuncSetAttribute(attn_kernel, cudaFuncAttributeMaxDynamicSharedMemorySize,
                         ATTN_SMEM_BYTES);
    cudaFuncSetAttribute(gemm_mma, cudaFuncAttributeMaxDynamicSharedMemorySize,
                         MMA_SMEM);

    // 1) layernorm + weight transposes
    ln_kernel<<<NL, 64>>>(m, gamma, beta);
    dim3 trb(32, 8), trg(8, 8);
    tr_kernel<<<trg, trb>>>(Wq, wt + 0 * 65536);
    tr_kernel<<<trg, trb>>>(Wk, wt + 1 * 65536);
    tr_kernel<<<trg, trb>>>(Wv, wt + 2 * 65536);
    tr_kernel<<<trg, trb>>>(Wg, wt + 3 * 65536);
    tr_kernel<<<trg, trb>>>(Wo, wt + 4 * 65536);

    // 2) projections via tf32 mma.sync
    gemm_mma<<<NL / 128, 512, MMA_SMEM>>>(x, wt + 0 * 65536, nullptr, q, 0);
    gemm_mma<<<NL / 128, 512, MMA_SMEM>>>(x, wt + 1 * 65536, nullptr, k, 0);
    gemm_mma<<<NL / 128, 512, MMA_SMEM>>>(x, wt + 2 * 65536, nullptr, v, 0);
    gemm_mma<<<NL / 128, 512, MMA_SMEM>>>(x, wt + 3 * 65536, bg, g, 1);

    // 3) attention per (l, h)
    attn_kernel<<<LRES * NHEAD, 256, ATTN_SMEM_BYTES>>>();

    // 4) output projection + bias
    gemm_mma<<<NL / 128, 512, MMA_SMEM>>>(o, wt + 4 * 65536, bo, out, 2);
}

// round 12
// speedup vs baseline: 2.3880x; 1.0048x over previous
#include <cuda_runtime.h>
#include <math.h>
#include <stdint.h>

#define NSEQ  256
#define LRES  384
#define MDIM  256
#define NHEAD 8
#define CDIM  32
#define HC    256
#define NL    (NSEQ * LRES)            // 98304
#define SQC   0.17677669529663687f     // 1/sqrt(32)

typedef unsigned long long ull;

// -------- scratch (static device globals; no allocations allowed) --------
__device__ float g_x[(size_t)NL * MDIM];   // layernormed input
__device__ float g_q[(size_t)NL * HC];
__device__ float g_k[(size_t)NL * HC];
__device__ float g_v[(size_t)NL * HC];
__device__ float g_g[(size_t)NL * HC];     // sigmoid gate (activation applied)
__device__ float g_o[(size_t)NL * HC];     // gated attention output
__device__ float g_wt[5 * 256 * 256];      // transposed weights [n][k]

// -------- f32x2 helpers --------
__device__ __forceinline__ void fma2(ull& d, ull a, ull b) {
    asm("fma.rn.f32x2 %0, %1, %2, %0;" : "+l"(d) : "l"(a), "l"(b));
}
__device__ __forceinline__ float2 unpk(ull v) {
    float2 f;
    asm("mov.b64 {%0, %1}, %2;" : "=f"(f.x), "=f"(f.y) : "l"(v));
    return f;
}

// -------- tf32 helpers (mma.sync path: no arch-suffix, works on compute_103) --------
__device__ __forceinline__ float tf32r(float f) {
    uint32_t u;
    asm("cvt.rna.tf32.f32 %0, %1;" : "=r"(u) : "f"(f));
    return __uint_as_float(u);
}
__device__ __forceinline__ void mma_16x8x8(float* c, const uint32_t* a, const uint32_t* b) {
    asm volatile(
        "mma.sync.aligned.m16n8k8.row.col.f32.tf32.tf32.f32 "
        "{%0,%1,%2,%3}, {%4,%5,%6,%7}, {%8,%9}, {%0,%1,%2,%3};"
        : "+f"(c[0]), "+f"(c[1]), "+f"(c[2]), "+f"(c[3])
        : "r"(a[0]), "r"(a[1]), "r"(a[2]), "r"(a[3]), "r"(b[0]), "r"(b[1]));
}

// ============================ LayerNorm ============================
__global__ void ln_kernel(const float* __restrict__ m,
                          const float* __restrict__ gamma,
                          const float* __restrict__ beta) {
    int row = blockIdx.x;
    const float4* mr = (const float4*)(m + (size_t)row * MDIM);
    float4* xr = (float4*)(g_x + (size_t)row * MDIM);
    int tid = threadIdx.x;

    float4 v = mr[tid];
    float s  = v.x + v.y + v.z + v.w;
    float ss = v.x * v.x + v.y * v.y + v.z * v.z + v.w * v.w;
    #pragma unroll
    for (int o = 16; o; o >>= 1) {
        s  += __shfl_xor_sync(0xffffffffu, s,  o);
        ss += __shfl_xor_sync(0xffffffffu, ss, o);
    }
    __shared__ float sh[4];
    if ((tid & 31) == 0) { sh[tid >> 5] = s; sh[2 + (tid >> 5)] = ss; }
    __syncthreads();
    s  = sh[0] + sh[1];
    ss = sh[2] + sh[3];
    float mu  = s * (1.0f / MDIM);
    float var = ss * (1.0f / MDIM) - mu * mu;
    float inv = rsqrtf(var + 1e-5f);

    float4 gm = ((const float4*)gamma)[tid];
    float4 bt = ((const float4*)beta)[tid];
    float4 r;
    r.x = (v.x - mu) * inv * gm.x + bt.x;
    r.y = (v.y - mu) * inv * gm.y + bt.y;
    r.z = (v.z - mu) * inv * gm.z + bt.z;
    r.w = (v.w - mu) * inv * gm.w + bt.w;
    xr[tid] = r;
}

// ============================ weight transpose ============================
__global__ void tr_kernel(const float* __restrict__ W, float* __restrict__ Wt) {
    __shared__ float t[32][33];
    int bx = blockIdx.x * 32, by = blockIdx.y * 32;
    int x = threadIdx.x, y = threadIdx.y;
    #pragma unroll
    for (int i = 0; i < 32; i += 8)
        t[y + i][x] = W[(size_t)(by + y + i) * 256 + bx + x];
    __syncthreads();
    #pragma unroll
    for (int i = 0; i < 32; i += 8)
        Wt[(size_t)(bx + y + i) * 256 + by + x] = t[x][y + i];
}

// ============================ tf32 mma.sync GEMM ============================
// C[M,256] = A[M,256] (row-major) * Bt[256 n][256 k] (K-major, pre-transposed).
// CTA: 512 threads (16 warps, 2x8), tile 128x256; warp-tile 64x32.
// K in 4 chunks of 64, smem stride 68 (conflict-free staging + frag loads).
// epi_mode: 0 plain, 1 sigmoid(v + bias), 2 v + bias
#define AS_ST 68
#define AS_F  (128 * AS_ST)            // 8704 floats
#define BS_F  (256 * AS_ST)            // 17408 floats
#define MMA_SMEM ((AS_F + BS_F) * 4)   // 104448 bytes

__global__ __launch_bounds__(512, 1)
void gemm_mma(const float* __restrict__ A,
              const float* __restrict__ Bt,
              const float* __restrict__ bias,
              float* __restrict__ Cout,
              int epi_mode) {
    extern __shared__ float sh[];
    float* As = sh;
    float* Bs = sh + AS_F;

    int tid = threadIdx.x;
    int wid = tid >> 5, lane = tid & 31;
    int gq = lane >> 2, tig = lane & 3;
    int wm = wid >> 3, wn = wid & 7;
    int bm = blockIdx.x * 128;

    float acc[4][4][4];
    #pragma unroll
    for (int i = 0; i < 4; i++)
        #pragma unroll
        for (int j = 0; j < 4; j++)
            #pragma unroll
            for (int z = 0; z < 4; z++) acc[i][j][z] = 0.0f;

    for (int kc = 0; kc < 4; kc++) {
        int k0g = kc * 64;
        // stage A chunk: 128 rows x 64 k (8192 floats, 4 float4/thread)
        #pragma unroll
        for (int j = 0; j < 4; j++) {
            int idx = j * 512 + tid;
            int r = idx >> 4, c = (idx & 15) << 2;
            float4 d = *(const float4*)&A[(size_t)(bm + r) * 256 + k0g + c];
            float4 t = make_float4(tf32r(d.x), tf32r(d.y), tf32r(d.z), tf32r(d.w));
            *(float4*)&As[r * AS_ST + c] = t;
        }
        // stage B chunk: 256 n-rows x 64 k (16384 floats, 8 float4/thread)
        #pragma unroll
        for (int j = 0; j < 8; j++) {
            int idx = j * 512 + tid;
            int n = idx >> 4, c = (idx & 15) << 2;
            float4 d = *(const float4*)&Bt[(size_t)n * 256 + k0g + c];
            float4 t = make_float4(tf32r(d.x), tf32r(d.y), tf32r(d.z), tf32r(d.w));
            *(float4*)&Bs[n * AS_ST + c] = t;
        }
        __syncthreads();

        #pragma unroll
        for (int kk = 0; kk < 8; kk++) {
            int k0 = kk * 8;
            uint32_t af[4][4], bf[4][2];
            #pragma unroll
            for (int mb = 0; mb < 4; mb++) {
                int r0 = wm * 64 + mb * 16 + gq;
                af[mb][0] = __float_as_uint(As[r0 * AS_ST + k0 + tig]);
                af[mb][1] = __float_as_uint(As[(r0 + 8) * AS_ST + k0 + tig]);
                af[mb][2] = __float_as_uint(As[r0 * AS_ST + k0 + tig + 4]);
                af[mb][3] = __float_as_uint(As[(r0 + 8) * AS_ST + k0 + tig + 4]);
            }
            #pragma unroll
            for (int nb = 0; nb < 4; nb++) {
                int n0 = wn * 32 + nb * 8 + gq;
                bf[nb][0] = __float_as_uint(Bs[n0 * AS_ST + k0 + tig]);
                bf[nb][1] = __float_as_uint(Bs[n0 * AS_ST + k0 + tig + 4]);
            }
            #pragma unroll
            for (int mb = 0; mb < 4; mb++)
                #pragma unroll
                for (int nb = 0; nb < 4; nb++)
                    mma_16x8x8(acc[mb][nb], af[mb], bf[nb]);
        }
        __syncthreads();
    }

    // epilogue: c0=(g,2t), c1=(g,2t+1), c2=(g+8,2t), c3=(g+8,2t+1)
    #pragma unroll
    for (int mb = 0; mb < 4; mb++) {
        int row = bm + wm * 64 + mb * 16 + gq;
        #pragma unroll
        for (int nb = 0; nb < 4; nb++) {
            int col = wn * 32 + nb * 8 + 2 * tig;
            float b0 = 0.f, b1 = 0.f;
            if (epi_mode != 0) { b0 = bias[col]; b1 = bias[col + 1]; }
            float v0 = acc[mb][nb][0], v1 = acc[mb][nb][1];
            float v2 = acc[mb][nb][2], v3 = acc[mb][nb][3];
            if (epi_mode == 1) {
                v0 = 1.0f / (1.0f + __expf(-(v0 + b0)));
                v1 = 1.0f / (1.0f + __expf(-(v1 + b1)));
                v2 = 1.0f / (1.0f + __expf(-(v2 + b0)));
                v3 = 1.0f / (1.0f + __expf(-(v3 + b1)));
            } else if (epi_mode == 2) {
                v0 += b0; v1 += b1; v2 += b0; v3 += b1;
            }
            *(float2*)&Cout[(size_t)row * 256 + col]       = make_float2(v0, v1);
            *(float2*)&Cout[(size_t)(row + 8) * 256 + col] = make_float2(v2, v3);
        }
    }
}

// ============================ Attention ============================
#define KST 36
#define VST 260
#define PST 260
#define K_SM_F  (256 * KST)
#define V_SM_F  (32 * VST)
#define P_SM_F  (32 * PST)
#define Q_SM_F  (32 * 32)
#define ATTN_SMEM_BYTES ((K_SM_F + V_SM_F + P_SM_F + Q_SM_F) * 4)   // 107520

__global__ __launch_bounds__(256, 2) void attn_kernel() {
    extern __shared__ float sm[];
    float* k_sm = sm;
    float* v_sm = sm + K_SM_F;
    float* p_sm = sm + K_SM_F + V_SM_F;
    float* q_sm = sm + K_SM_F + V_SM_F + P_SM_F;

    int l = blockIdx.x >> 3;
    int h = blockIdx.x & 7;
    int tid = threadIdx.x;
    int w = tid >> 5, lane = tid & 31;

    size_t head_off = (size_t)h * CDIM;

    for (int idx = tid; idx < 256 * 32; idx += 256) {
        int t = idx >> 5, c = idx & 31;
        size_t gi = ((size_t)(t * LRES + l)) * HC + head_off + c;
        k_sm[t * KST + c] = g_k[gi];
        v_sm[c * VST + t] = g_v[gi];
    }
    __syncthreads();

    for (int it = 0; it < 8; it++) {
        int s0 = it * 32 + w * 4;
        int prow = w * 4;

        #pragma unroll
        for (int r = 0; r < 4; r++) {
            size_t qi = ((size_t)((s0 + r) * LRES + l)) * HC + head_off + lane;
            q_sm[(prow + r) * 32 + lane] = g_q[qi];
        }
        __syncwarp();

        ull sc2[8][4];
        #pragma unroll
        for (int i = 0; i < 8; i++)
            #pragma unroll
            for (int r = 0; r < 4; r++) sc2[i][r] = 0ULL;

        #pragma unroll
        for (int cb = 0; cb < 4; cb++) {
            ull q2[4][4];
            #pragma unroll
            for (int r = 0; r < 4; r++) {
                ulonglong2 t0 = *(ulonglong2*)&q_sm[(prow + r) * 32 + cb * 8];
                ulonglong2 t1 = *(ulonglong2*)&q_sm[(prow + r) * 32 + cb * 8 + 4];
                q2[r][0] = t0.x; q2[r][1] = t0.y; q2[r][2] = t1.x; q2[r][3] = t1.y;
            }
            #pragma unroll
            for (int i = 0; i < 8; i++) {
                int t = i * 32 + lane;
                ulonglong2 k0 = *(ulonglong2*)&k_sm[t * KST + cb * 8];
                ulonglong2 k1 = *(ulonglong2*)&k_sm[t * KST + cb * 8 + 4];
                ull k2[4] = { k0.x, k0.y, k1.x, k1.y };
                #pragma unroll
                for (int r = 0; r < 4; r++) {
                    fma2(sc2[i][r], k2[0], q2[r][0]);
                    fma2(sc2[i][r], k2[1], q2[r][1]);
                    fma2(sc2[i][r], k2[2], q2[r][2]);
                    fma2(sc2[i][r], k2[3], q2[r][3]);
                }
            }
        }

        float sc[8][4];
        #pragma unroll
        for (int i = 0; i < 8; i++)
            #pragma unroll
            for (int r = 0; r < 4; r++) {
                float2 f = unpk(sc2[i][r]);
                sc[i][r] = (f.x + f.y) * SQC;
            }

        #pragma unroll
        for (int r = 0; r < 4; r++) {
            float mx = sc[0][r];
            #pragma unroll
            for (int i = 1; i < 8; i++) mx = fmaxf(mx, sc[i][r]);
            #pragma unroll
            for (int o = 16; o; o >>= 1)
                mx = fmaxf(mx, __shfl_xor_sync(0xffffffffu, mx, o));
            float sum = 0.0f;
            #pragma unroll
            for (int i = 0; i < 8; i++) {
                sc[i][r] = __expf(sc[i][r] - mx);
                sum += sc[i][r];
            }
            #pragma unroll
            for (int o = 16; o; o >>= 1)
                sum += __shfl_xor_sync(0xffffffffu, sum, o);
            float rinv = 1.0f / sum;
            #pragma unroll
            for (int i = 0; i < 8; i++)
                p_sm[(prow + r) * PST + i * 32 + lane] = sc[i][r] * rinv;
        }
        __syncwarp();

        ull oa[4] = { 0ULL, 0ULL, 0ULL, 0ULL };
        #pragma unroll
        for (int tq = 0; tq < 32; tq++) {
            ulonglong2 v0 = *(ulonglong2*)&v_sm[lane * VST + tq * 8];
            ulonglong2 v1 = *(ulonglong2*)&v_sm[lane * VST + tq * 8 + 4];
            ull v2[4] = { v0.x, v0.y, v1.x, v1.y };
            #pragma unroll
            for (int r = 0; r < 4; r++) {
                ulonglong2 p0 = *(ulonglong2*)&p_sm[(prow + r) * PST + tq * 8];
                ulonglong2 p1 = *(ulonglong2*)&p_sm[(prow + r) * PST + tq * 8 + 4];
                fma2(oa[r], v2[0], p0.x);
                fma2(oa[r], v2[1], p0.y);
                fma2(oa[r], v2[2], p1.x);
                fma2(oa[r], v2[3], p1.y);
            }
        }

        #pragma unroll
        for (int r = 0; r < 4; r++) {
            float2 f = unpk(oa[r]);
            float ov = f.x + f.y;
            size_t qi = ((size_t)((s0 + r) * LRES + l)) * HC + head_off + lane;
            g_o[qi] = ov * g_g[qi];
        }
        __syncwarp();
    }
}

// ============================ launch ============================
extern "C" void kernel_launch(void* const* d_in, const int* in_sizes, int n_in,
                              void* d_out, int out_size) {
    (void)in_sizes; (void)n_in; (void)out_size;
    const float* m     = (const float*)d_in[0];
    const float* gamma = (const float*)d_in[1];
    const float* beta  = (const float*)d_in[2];
    const float* Wq    = (const float*)d_in[3];
    const float* Wk    = (const float*)d_in[4];
    const float* Wv    = (const float*)d_in[5];
    const float* Wg    = (const float*)d_in[6];
    const float* bg    = (const float*)d_in[7];
    const float* Wo    = (const float*)d_in[8];
    const float* bo    = (const float*)d_in[9];
    float* out = (float*)d_out;

    float *x, *q, *k, *v, *g, *o, *wt;
    cudaGetSymbolAddress((void**)&x, g_x);
    cudaGetSymbolAddress((void**)&q, g_q);
    cudaGetSymbolAddress((void**)&k, g_k);
    cudaGetSymbolAddress((void**)&v, g_v);
    cudaGetSymbolAddress((void**)&g, g_g);
    cudaGetSymbolAddress((void**)&o, g_o);
    cudaGetSymbolAddress((void**)&wt, g_wt);

    cudaFuncSetAttribute(attn_kernel, cudaFuncAttributeMaxDynamicSharedMemorySize,
                         ATTN_SMEM_BYTES);
    cudaFuncSetAttribute(gemm_mma, cudaFuncAttributeMaxDynamicSharedMemorySize,
                         MMA_SMEM);

    // 1) layernorm + weight transposes
    ln_kernel<<<NL, 64>>>(m, gamma, beta);
    dim3 trb(32, 8), trg(8, 8);
    tr_kernel<<<trg, trb>>>(Wq, wt + 0 * 65536);
    tr_kernel<<<trg, trb>>>(Wk, wt + 1 * 65536);
    tr_kernel<<<trg, trb>>>(Wv, wt + 2 * 65536);
    tr_kernel<<<trg, trb>>>(Wg, wt + 3 * 65536);
    tr_kernel<<<trg, trb>>>(Wo, wt + 4 * 65536);

    // 2) projections via tf32 mma.sync
    gemm_mma<<<NL / 128, 512, MMA_SMEM>>>(x, wt + 0 * 65536, nullptr, q, 0);
    gemm_mma<<<NL / 128, 512, MMA_SMEM>>>(x, wt + 1 * 65536, nullptr, k, 0);
    gemm_mma<<<NL / 128, 512, MMA_SMEM>>>(x, wt + 2 * 65536, nullptr, v, 0);
    gemm_mma<<<NL / 128, 512, MMA_SMEM>>>(x, wt + 3 * 65536, bg, g, 1);

    // 3) attention per (l, h)
    attn_kernel<<<LRES * NHEAD, 256, ATTN_SMEM_BYTES>>>();

    // 4) output projection + bias
    gemm_mma<<<NL / 128, 512, MMA_SMEM>>>(o, wt + 4 * 65536, bo, out, 2);
}

// round 14
// speedup vs baseline: 2.5793x; 1.0801x over previous
#include <cuda_runtime.h>
#include <math.h>
#include <stdint.h>

#define NSEQ  256
#define LRES  384
#define MDIM  256
#define NHEAD 8
#define CDIM  32
#define HC    256
#define NL    (NSEQ * LRES)            // 98304
#define SQC   0.17677669529663687f     // 1/sqrt(32)

typedef unsigned long long ull;

// -------- scratch (static device globals; no allocations allowed) --------
__device__ float g_x[(size_t)NL * MDIM];   // layernormed input
__device__ float g_q[(size_t)NL * HC];
__device__ float g_k[(size_t)NL * HC];
__device__ float g_v[(size_t)NL * HC];
__device__ float g_g[(size_t)NL * HC];     // sigmoid gate (activation applied)
__device__ float g_o[(size_t)NL * HC];     // gated attention output
__device__ float g_wt[5 * 256 * 256];      // transposed weights [n][k]

// -------- tf32 helpers (mma.sync path: no arch-suffix, works on compute_103) --------
__device__ __forceinline__ float tf32r(float f) {
    uint32_t u;
    asm("cvt.rna.tf32.f32 %0, %1;" : "=r"(u) : "f"(f));
    return __uint_as_float(u);
}
__device__ __forceinline__ void mma_16x8x8(float* c, const uint32_t* a, const uint32_t* b) {
    asm volatile(
        "mma.sync.aligned.m16n8k8.row.col.f32.tf32.tf32.f32 "
        "{%0,%1,%2,%3}, {%4,%5,%6,%7}, {%8,%9}, {%0,%1,%2,%3};"
        : "+f"(c[0]), "+f"(c[1]), "+f"(c[2]), "+f"(c[3])
        : "r"(a[0]), "r"(a[1]), "r"(a[2]), "r"(a[3]), "r"(b[0]), "r"(b[1]));
}

// ============================ LayerNorm ============================
__global__ void ln_kernel(const float* __restrict__ m,
                          const float* __restrict__ gamma,
                          const float* __restrict__ beta) {
    int row = blockIdx.x;
    const float4* mr = (const float4*)(m + (size_t)row * MDIM);
    float4* xr = (float4*)(g_x + (size_t)row * MDIM);
    int tid = threadIdx.x;

    float4 v = mr[tid];
    float s  = v.x + v.y + v.z + v.w;
    float ss = v.x * v.x + v.y * v.y + v.z * v.z + v.w * v.w;
    #pragma unroll
    for (int o = 16; o; o >>= 1) {
        s  += __shfl_xor_sync(0xffffffffu, s,  o);
        ss += __shfl_xor_sync(0xffffffffu, ss, o);
    }
    __shared__ float sh[4];
    if ((tid & 31) == 0) { sh[tid >> 5] = s; sh[2 + (tid >> 5)] = ss; }
    __syncthreads();
    s  = sh[0] + sh[1];
    ss = sh[2] + sh[3];
    float mu  = s * (1.0f / MDIM);
    float var = ss * (1.0f / MDIM) - mu * mu;
    float inv = rsqrtf(var + 1e-5f);

    float4 gm = ((const float4*)gamma)[tid];
    float4 bt = ((const float4*)beta)[tid];
    float4 r;
    r.x = (v.x - mu) * inv * gm.x + bt.x;
    r.y = (v.y - mu) * inv * gm.y + bt.y;
    r.z = (v.z - mu) * inv * gm.z + bt.z;
    r.w = (v.w - mu) * inv * gm.w + bt.w;
    xr[tid] = r;
}

// ============================ weight transpose ============================
__global__ void tr_kernel(const float* __restrict__ W, float* __restrict__ Wt) {
    __shared__ float t[32][33];
    int bx = blockIdx.x * 32, by = blockIdx.y * 32;
    int x = threadIdx.x, y = threadIdx.y;
    #pragma unroll
    for (int i = 0; i < 32; i += 8)
        t[y + i][x] = W[(size_t)(by + y + i) * 256 + bx + x];
    __syncthreads();
    #pragma unroll
    for (int i = 0; i < 32; i += 8)
        Wt[(size_t)(bx + y + i) * 256 + by + x] = t[x][y + i];
}

// ============================ tf32 mma.sync GEMM ============================
// C[M,256] = A[M,256] (row-major) * Bt[256 n][256 k] (K-major, pre-transposed).
// CTA: 512 threads (16 warps, 2x8), tile 128x256; warp-tile 64x32.
// epi_mode: 0 plain, 1 sigmoid(v + bias), 2 v + bias
#define AS_ST 68
#define AS_F  (128 * AS_ST)            // 8704 floats
#define BS_F  (256 * AS_ST)            // 17408 floats
#define MMA_SMEM ((AS_F + BS_F) * 4)   // 104448 bytes

__global__ __launch_bounds__(512, 1)
void gemm_mma(const float* __restrict__ A,
              const float* __restrict__ Bt,
              const float* __restrict__ bias,
              float* __restrict__ Cout,
              int epi_mode) {
    extern __shared__ float sh[];
    float* As = sh;
    float* Bs = sh + AS_F;

    int tid = threadIdx.x;
    int wid = tid >> 5, lane = tid & 31;
    int gq = lane >> 2, tig = lane & 3;
    int wm = wid >> 3, wn = wid & 7;
    int bm = blockIdx.x * 128;

    float acc[4][4][4];
    #pragma unroll
    for (int i = 0; i < 4; i++)
        #pragma unroll
        for (int j = 0; j < 4; j++)
            #pragma unroll
            for (int z = 0; z < 4; z++) acc[i][j][z] = 0.0f;

    for (int kc = 0; kc < 4; kc++) {
        int k0g = kc * 64;
        #pragma unroll
        for (int j = 0; j < 4; j++) {
            int idx = j * 512 + tid;
            int r = idx >> 4, c = (idx & 15) << 2;
            float4 d = *(const float4*)&A[(size_t)(bm + r) * 256 + k0g + c];
            float4 t = make_float4(tf32r(d.x), tf32r(d.y), tf32r(d.z), tf32r(d.w));
            *(float4*)&As[r * AS_ST + c] = t;
        }
        #pragma unroll
        for (int j = 0; j < 8; j++) {
            int idx = j * 512 + tid;
            int n = idx >> 4, c = (idx & 15) << 2;
            float4 d = *(const float4*)&Bt[(size_t)n * 256 + k0g + c];
            float4 t = make_float4(tf32r(d.x), tf32r(d.y), tf32r(d.z), tf32r(d.w));
            *(float4*)&Bs[n * AS_ST + c] = t;
        }
        __syncthreads();

        #pragma unroll
        for (int kk = 0; kk < 8; kk++) {
            int k0 = kk * 8;
            uint32_t af[4][4], bf[4][2];
            #pragma unroll
            for (int mb = 0; mb < 4; mb++) {
                int r0 = wm * 64 + mb * 16 + gq;
                af[mb][0] = __float_as_uint(As[r0 * AS_ST + k0 + tig]);
                af[mb][1] = __float_as_uint(As[(r0 + 8) * AS_ST + k0 + tig]);
                af[mb][2] = __float_as_uint(As[r0 * AS_ST + k0 + tig + 4]);
                af[mb][3] = __float_as_uint(As[(r0 + 8) * AS_ST + k0 + tig + 4]);
            }
            #pragma unroll
            for (int nb = 0; nb < 4; nb++) {
                int n0 = wn * 32 + nb * 8 + gq;
                bf[nb][0] = __float_as_uint(Bs[n0 * AS_ST + k0 + tig]);
                bf[nb][1] = __float_as_uint(Bs[n0 * AS_ST + k0 + tig + 4]);
            }
            #pragma unroll
            for (int mb = 0; mb < 4; mb++)
                #pragma unroll
                for (int nb = 0; nb < 4; nb++)
                    mma_16x8x8(acc[mb][nb], af[mb], bf[nb]);
        }
        __syncthreads();
    }

    #pragma unroll
    for (int mb = 0; mb < 4; mb++) {
        int row = bm + wm * 64 + mb * 16 + gq;
        #pragma unroll
        for (int nb = 0; nb < 4; nb++) {
            int col = wn * 32 + nb * 8 + 2 * tig;
            float b0 = 0.f, b1 = 0.f;
            if (epi_mode != 0) { b0 = bias[col]; b1 = bias[col + 1]; }
            float v0 = acc[mb][nb][0], v1 = acc[mb][nb][1];
            float v2 = acc[mb][nb][2], v3 = acc[mb][nb][3];
            if (epi_mode == 1) {
                v0 = 1.0f / (1.0f + __expf(-(v0 + b0)));
                v1 = 1.0f / (1.0f + __expf(-(v1 + b1)));
                v2 = 1.0f / (1.0f + __expf(-(v2 + b0)));
                v3 = 1.0f / (1.0f + __expf(-(v3 + b1)));
            } else if (epi_mode == 2) {
                v0 += b0; v1 += b1; v2 += b0; v3 += b1;
            }
            *(float2*)&Cout[(size_t)row * 256 + col]       = make_float2(v0, v1);
            *(float2*)&Cout[(size_t)(row + 8) * 256 + col] = make_float2(v2, v3);
        }
    }
}

// ============================ Attention (tf32 mma.sync) ============================
// 1 CTA (256 thr, 8 warps) per (l, h). K,V^T tf32-staged once; 2 s-tiles of 128.
// QK^T: warps 2x4, warp-tile 64x64. Softmax in smem (unnormalized exp, tf32).
// PV: warp-tile 16x32, K=256. Epilogue: *1/rowsum * gate.
#define AKST 36                         // k_sm/q_sm stride (36 mod 32 = 4 -> conflict-free)
#define AVST 260                        // v^T stride
#define ASST 260                        // score stride
#define AK_F (256 * AKST)               // 9216
#define AV_F (32 * AVST)                // 8320
#define AQ_F (128 * AKST)               // 4608
#define ASF  (128 * ASST)               // 33280
#define ATTN_SMEM ((AK_F + AV_F + AQ_F + ASF + 128) * 4)   // 222208 bytes

__global__ __launch_bounds__(256, 1) void attn_mma() {
    extern __shared__ float sm[];
    float* k_sm = sm;                   // [256][36]  K, row=t, col=c (tf32)
    float* v_sm = k_sm + AK_F;          // [32][260]  V^T, row=c, col=t (tf32)
    float* q_sm = v_sm + AV_F;          // [128][36]  Q tile (tf32)
    float* s_sm = q_sm + AQ_F;          // [128][260] scores / probs
    float* rsum = s_sm + ASF;           // [128] 1/rowsum

    int l = blockIdx.x >> 3;
    int h = blockIdx.x & 7;
    int tid = threadIdx.x;
    int wid = tid >> 5, lane = tid & 31;
    int gq = lane >> 2, tig = lane & 3;
    size_t hoff = (size_t)h * CDIM;

    // ---- stage K (256x32) and V^T (32x256), tf32 ----
    for (int i = tid; i < 2048; i += 256) {        // K: float4 granularity
        int t = i >> 3, c = (i & 7) << 2;
        float4 d = *(const float4*)&g_k[((size_t)(t * LRES + l)) * HC + hoff + c];
        float4 r = make_float4(tf32r(d.x), tf32r(d.y), tf32r(d.z), tf32r(d.w));
        *(float4*)&k_sm[t * AKST + c] = r;
    }
    for (int i = tid; i < 8192; i += 256) {        // V transpose (scalar)
        int t = i >> 5, c = i & 31;
        v_sm[c * AVST + t] = tf32r(g_v[((size_t)(t * LRES + l)) * HC + hoff + c]);
    }
    __syncthreads();

    for (int st = 0; st < 2; st++) {
        int sbase = st * 128;

        // ---- stage Q tile (128x32 = 1024 float4, 8 float4 per row), tf32 ----
        for (int i = tid; i < 1024; i += 256) {
            int r = i >> 3, c = (i & 7) << 2;
            float4 d = *(const float4*)&g_q[((size_t)((sbase + r) * LRES + l)) * HC + hoff + c];
            float4 v = make_float4(tf32r(d.x), tf32r(d.y), tf32r(d.z), tf32r(d.w));
            *(float4*)&q_sm[r * AKST + c] = v;
        }
        __syncthreads();

        // ---- QK^T: S[128,256] = Q[128,32] @ K^T; warps 2x4, tile 64x64 ----
        {
            int wm = wid >> 2, wn = wid & 3;
            float acc[4][8][4];
            #pragma unroll
            for (int i = 0; i < 4; i++)
                #pragma unroll
                for (int j = 0; j < 8; j++)
                    #pragma unroll
                    for (int z = 0; z < 4; z++) acc[i][j][z] = 0.0f;

            #pragma unroll
            for (int kk = 0; kk < 4; kk++) {
                int k0 = kk * 8;
                uint32_t af[4][4], bf[8][2];
                #pragma unroll
                for (int mb = 0; mb < 4; mb++) {
                    int r0 = wm * 64 + mb * 16 + gq;
                    af[mb][0] = __float_as_uint(q_sm[r0 * AKST + k0 + tig]);
                    af[mb][1] = __float_as_uint(q_sm[(r0 + 8) * AKST + k0 + tig]);
                    af[mb][2] = __float_as_uint(q_sm[r0 * AKST + k0 + tig + 4]);
                    af[mb][3] = __float_as_uint(q_sm[(r0 + 8) * AKST + k0 + tig + 4]);
                }
                #pragma unroll
                for (int nb = 0; nb < 8; nb++) {
                    int n0 = wn * 64 + nb * 8 + gq;
                    bf[nb][0] = __float_as_uint(k_sm[n0 * AKST + k0 + tig]);
                    bf[nb][1] = __float_as_uint(k_sm[n0 * AKST + k0 + tig + 4]);
                }
                #pragma unroll
                for (int mb = 0; mb < 4; mb++)
                    #pragma unroll
                    for (int nb = 0; nb < 8; nb++)
                        mma_16x8x8(acc[mb][nb], af[mb], bf[nb]);
            }
            // write scaled scores to s_sm
            #pragma unroll
            for (int mb = 0; mb < 4; mb++) {
                int row = wm * 64 + mb * 16 + gq;
                #pragma unroll
                for (int nb = 0; nb < 8; nb++) {
                    int col = wn * 64 + nb * 8 + 2 * tig;
                    *(float2*)&s_sm[row * ASST + col] =
                        make_float2(acc[mb][nb][0] * SQC, acc[mb][nb][1] * SQC);
                    *(float2*)&s_sm[(row + 8) * ASST + col] =
                        make_float2(acc[mb][nb][2] * SQC, acc[mb][nb][3] * SQC);
                }
            }
        }
        __syncthreads();

        // ---- softmax: warp wid owns rows wid*16 .. +15 ----
        for (int rr = 0; rr < 16; rr++) {
            int row = wid * 16 + rr;
            float vv[8];
            #pragma unroll
            for (int i = 0; i < 8; i++) vv[i] = s_sm[row * ASST + i * 32 + lane];
            float mx = vv[0];
            #pragma unroll
            for (int i = 1; i < 8; i++) mx = fmaxf(mx, vv[i]);
            #pragma unroll
            for (int o = 16; o; o >>= 1)
                mx = fmaxf(mx, __shfl_xor_sync(0xffffffffu, mx, o));
            float sum = 0.0f;
            #pragma unroll
            for (int i = 0; i < 8; i++) { vv[i] = __expf(vv[i] - mx); sum += vv[i]; }
            #pragma unroll
            for (int o = 16; o; o >>= 1)
                sum += __shfl_xor_sync(0xffffffffu, sum, o);
            #pragma unroll
            for (int i = 0; i < 8; i++)
                s_sm[row * ASST + i * 32 + lane] = tf32r(vv[i]);
            if (lane == 0) rsum[row] = 1.0f / sum;
        }
        __syncthreads();

        // ---- PV: O[128,32] = P[128,256] @ V; warp-tile 16x32 ----
        {
            float acc2[4][4];
            #pragma unroll
            for (int j = 0; j < 4; j++)
                #pragma unroll
                for (int z = 0; z < 4; z++) acc2[j][z] = 0.0f;

            int r0 = wid * 16 + gq;
            #pragma unroll
            for (int kk = 0; kk < 32; kk++) {
                int k0 = kk * 8;
                uint32_t af[4], bf[4][2];
                af[0] = __float_as_uint(s_sm[r0 * ASST + k0 + tig]);
                af[1] = __float_as_uint(s_sm[(r0 + 8) * ASST + k0 + tig]);
                af[2] = __float_as_uint(s_sm[r0 * ASST + k0 + tig + 4]);
                af[3] = __float_as_uint(s_sm[(r0 + 8) * ASST + k0 + tig + 4]);
                #pragma unroll
                for (int nb = 0; nb < 4; nb++) {
                    int n0 = nb * 8 + gq;
                    bf[nb][0] = __float_as_uint(v_sm[n0 * AVST + k0 + tig]);
                    bf[nb][1] = __float_as_uint(v_sm[n0 * AVST + k0 + tig + 4]);
                }
                #pragma unroll
                for (int nb = 0; nb < 4; nb++)
                    mma_16x8x8(acc2[nb], af, bf[nb]);
            }

            // epilogue: normalize, gate, store
            float ri0 = rsum[wid * 16 + gq];
            float ri1 = rsum[wid * 16 + gq + 8];
            int srow0 = sbase + wid * 16 + gq;
            #pragma unroll
            for (int nb = 0; nb < 4; nb++) {
                int col = nb * 8 + 2 * tig;
                size_t o0 = ((size_t)(srow0 * LRES + l)) * HC + hoff + col;
                size_t o1 = ((size_t)((srow0 + 8) * LRES + l)) * HC + hoff + col;
                float2 gg0 = *(const float2*)&g_g[o0];
                float2 gg1 = *(const float2*)&g_g[o1];
                *(float2*)&g_o[o0] = make_float2(acc2[nb][0] * ri0 * gg0.x,
                                                 acc2[nb][1] * ri0 * gg0.y);
                *(float2*)&g_o[o1] = make_float2(acc2[nb][2] * ri1 * gg1.x,
                                                 acc2[nb][3] * ri1 * gg1.y);
            }
        }
        __syncthreads();   // protect q_sm/s_sm before next s-tile
    }
}

// ============================ launch ============================
extern "C" void kernel_launch(void* const* d_in, const int* in_sizes, int n_in,
                              void* d_out, int out_size) {
    (void)in_sizes; (void)n_in; (void)out_size;
    const float* m     = (const float*)d_in[0];
    const float* gamma = (const float*)d_in[1];
    const float* beta  = (const float*)d_in[2];
    const float* Wq    = (const float*)d_in[3];
    const float* Wk    = (const float*)d_in[4];
    const float* Wv    = (const float*)d_in[5];
    const float* Wg    = (const float*)d_in[6];
    const float* bg    = (const float*)d_in[7];
    const float* Wo    = (const float*)d_in[8];
    const float* bo    = (const float*)d_in[9];
    float* out = (float*)d_out;

    float *x, *q, *k, *v, *g, *o, *wt;
    cudaGetSymbolAddress((void**)&x, g_x);
    cudaGetSymbolAddress((void**)&q, g_q);
    cudaGetSymbolAddress((void**)&k, g_k);
    cudaGetSymbolAddress((void**)&v, g_v);
    cudaGetSymbolAddress((void**)&g, g_g);
    cudaGetSymbolAddress((void**)&o, g_o);
    cudaGetSymbolAddress((void**)&wt, g_wt);

    cudaFuncSetAttribute(gemm_mma, cudaFuncAttributeMaxDynamicSharedMemorySize,
                         MMA_SMEM);
    cudaFuncSetAttribute(attn_mma, cudaFuncAttributeMaxDynamicSharedMemorySize,
                         ATTN_SMEM);

    // 1) layernorm + weight transposes
    ln_kernel<<<NL, 64>>>(m, gamma, beta);
    dim3 trb(32, 8), trg(8, 8);
    tr_kernel<<<trg, trb>>>(Wq, wt + 0 * 65536);
    tr_kernel<<<trg, trb>>>(Wk, wt + 1 * 65536);
    tr_kernel<<<trg, trb>>>(Wv, wt + 2 * 65536);
    tr_kernel<<<trg, trb>>>(Wg, wt + 3 * 65536);
    tr_kernel<<<trg, trb>>>(Wo, wt + 4 * 65536);

    // 2) projections via tf32 mma.sync
    gemm_mma<<<NL / 128, 512, MMA_SMEM>>>(x, wt + 0 * 65536, nullptr, q, 0);
    gemm_mma<<<NL / 128, 512, MMA_SMEM>>>(x, wt + 1 * 65536, nullptr, k, 0);
    gemm_mma<<<NL / 128, 512, MMA_SMEM>>>(x, wt + 2 * 65536, nullptr, v, 0);
    gemm_mma<<<NL / 128, 512, MMA_SMEM>>>(x, wt + 3 * 65536, bg, g, 1);

    // 3) attention per (l, h) via tf32 mma.sync
    attn_mma<<<LRES * NHEAD, 256, ATTN_SMEM>>>();

    // 4) output projection + bias
    gemm_mma<<<NL / 128, 512, MMA_SMEM>>>(o, wt + 4 * 65536, bo, out, 2);
}

// round 15
// speedup vs baseline: 2.8020x; 1.0863x over previous
#include <cuda_runtime.h>
#include <math.h>
#include <stdint.h>

#define NSEQ  256
#define LRES  384
#define MDIM  256
#define NHEAD 8
#define CDIM  32
#define HC    256
#define NL    (NSEQ * LRES)            // 98304
#define SQC   0.17677669529663687f     // 1/sqrt(32)

typedef unsigned long long ull;

// -------- scratch (static device globals; no allocations allowed) --------
__device__ float g_x[(size_t)NL * MDIM];   // layernormed input
__device__ float g_q[(size_t)NL * HC];
__device__ float g_k[(size_t)NL * HC];
__device__ float g_v[(size_t)NL * HC];
__device__ float g_g[(size_t)NL * HC];     // sigmoid gate (activation applied)
__device__ float g_o[(size_t)NL * HC];     // gated attention output
__device__ float g_wt[5 * 256 * 256];      // transposed weights [n][k]

// -------- tf32 helpers (mma.sync path: no arch-suffix, works on compute_103) --------
__device__ __forceinline__ float tf32r(float f) {
    uint32_t u;
    asm("cvt.rna.tf32.f32 %0, %1;" : "=r"(u) : "f"(f));
    return __uint_as_float(u);
}
__device__ __forceinline__ void mma_16x8x8(float* c, const uint32_t* a, const uint32_t* b) {
    asm volatile(
        "mma.sync.aligned.m16n8k8.row.col.f32.tf32.tf32.f32 "
        "{%0,%1,%2,%3}, {%4,%5,%6,%7}, {%8,%9}, {%0,%1,%2,%3};"
        : "+f"(c[0]), "+f"(c[1]), "+f"(c[2]), "+f"(c[3])
        : "r"(a[0]), "r"(a[1]), "r"(a[2]), "r"(a[3]), "r"(b[0]), "r"(b[1]));
}

// ============================ LayerNorm ============================
__global__ void ln_kernel(const float* __restrict__ m,
                          const float* __restrict__ gamma,
                          const float* __restrict__ beta) {
    int row = blockIdx.x;
    const float4* mr = (const float4*)(m + (size_t)row * MDIM);
    float4* xr = (float4*)(g_x + (size_t)row * MDIM);
    int tid = threadIdx.x;

    float4 v = mr[tid];
    float s  = v.x + v.y + v.z + v.w;
    float ss = v.x * v.x + v.y * v.y + v.z * v.z + v.w * v.w;
    #pragma unroll
    for (int o = 16; o; o >>= 1) {
        s  += __shfl_xor_sync(0xffffffffu, s,  o);
        ss += __shfl_xor_sync(0xffffffffu, ss, o);
    }
    __shared__ float sh[4];
    if ((tid & 31) == 0) { sh[tid >> 5] = s; sh[2 + (tid >> 5)] = ss; }
    __syncthreads();
    s  = sh[0] + sh[1];
    ss = sh[2] + sh[3];
    float mu  = s * (1.0f / MDIM);
    float var = ss * (1.0f / MDIM) - mu * mu;
    float inv = rsqrtf(var + 1e-5f);

    float4 gm = ((const float4*)gamma)[tid];
    float4 bt = ((const float4*)beta)[tid];
    float4 r;
    r.x = (v.x - mu) * inv * gm.x + bt.x;
    r.y = (v.y - mu) * inv * gm.y + bt.y;
    r.z = (v.z - mu) * inv * gm.z + bt.z;
    r.w = (v.w - mu) * inv * gm.w + bt.w;
    xr[tid] = r;
}

// ============================ weight transpose ============================
__global__ void tr_kernel(const float* __restrict__ W, float* __restrict__ Wt) {
    __shared__ float t[32][33];
    int bx = blockIdx.x * 32, by = blockIdx.y * 32;
    int x = threadIdx.x, y = threadIdx.y;
    #pragma unroll
    for (int i = 0; i < 32; i += 8)
        t[y + i][x] = W[(size_t)(by + y + i) * 256 + bx + x];
    __syncthreads();
    #pragma unroll
    for (int i = 0; i < 32; i += 8)
        Wt[(size_t)(bx + y + i) * 256 + by + x] = t[x][y + i];
}

// ============================ tf32 mma.sync GEMM ============================
// C[M,256] = A[M,256] (row-major) * Bt[256 n][256 k] (K-major, pre-transposed).
// CTA: 512 threads (16 warps, 2x8), tile 128x256; warp-tile 64x32.
// epi_mode: 0 plain, 1 sigmoid(v + bias), 2 v + bias
#define AS_ST 68
#define AS_F  (128 * AS_ST)            // 8704 floats
#define BS_F  (256 * AS_ST)            // 17408 floats
#define MMA_SMEM ((AS_F + BS_F) * 4)   // 104448 bytes

__global__ __launch_bounds__(512, 1)
void gemm_mma(const float* __restrict__ A,
              const float* __restrict__ Bt,
              const float* __restrict__ bias,
              float* __restrict__ Cout,
              int epi_mode) {
    extern __shared__ float sh[];
    float* As = sh;
    float* Bs = sh + AS_F;

    int tid = threadIdx.x;
    int wid = tid >> 5, lane = tid & 31;
    int gq = lane >> 2, tig = lane & 3;
    int wm = wid >> 3, wn = wid & 7;
    int bm = blockIdx.x * 128;

    float acc[4][4][4];
    #pragma unroll
    for (int i = 0; i < 4; i++)
        #pragma unroll
        for (int j = 0; j < 4; j++)
            #pragma unroll
            for (int z = 0; z < 4; z++) acc[i][j][z] = 0.0f;

    for (int kc = 0; kc < 4; kc++) {
        int k0g = kc * 64;
        #pragma unroll
        for (int j = 0; j < 4; j++) {
            int idx = j * 512 + tid;
            int r = idx >> 4, c = (idx & 15) << 2;
            float4 d = *(const float4*)&A[(size_t)(bm + r) * 256 + k0g + c];
            float4 t = make_float4(tf32r(d.x), tf32r(d.y), tf32r(d.z), tf32r(d.w));
            *(float4*)&As[r * AS_ST + c] = t;
        }
        #pragma unroll
        for (int j = 0; j < 8; j++) {
            int idx = j * 512 + tid;
            int n = idx >> 4, c = (idx & 15) << 2;
            float4 d = *(const float4*)&Bt[(size_t)n * 256 + k0g + c];
            float4 t = make_float4(tf32r(d.x), tf32r(d.y), tf32r(d.z), tf32r(d.w));
            *(float4*)&Bs[n * AS_ST + c] = t;
        }
        __syncthreads();

        #pragma unroll
        for (int kk = 0; kk < 8; kk++) {
            int k0 = kk * 8;
            uint32_t af[4][4], bf[4][2];
            #pragma unroll
            for (int mb = 0; mb < 4; mb++) {
                int r0 = wm * 64 + mb * 16 + gq;
                af[mb][0] = __float_as_uint(As[r0 * AS_ST + k0 + tig]);
                af[mb][1] = __float_as_uint(As[(r0 + 8) * AS_ST + k0 + tig]);
                af[mb][2] = __float_as_uint(As[r0 * AS_ST + k0 + tig + 4]);
                af[mb][3] = __float_as_uint(As[(r0 + 8) * AS_ST + k0 + tig + 4]);
            }
            #pragma unroll
            for (int nb = 0; nb < 4; nb++) {
                int n0 = wn * 32 + nb * 8 + gq;
                bf[nb][0] = __float_as_uint(Bs[n0 * AS_ST + k0 + tig]);
                bf[nb][1] = __float_as_uint(Bs[n0 * AS_ST + k0 + tig + 4]);
            }
            #pragma unroll
            for (int mb = 0; mb < 4; mb++)
                #pragma unroll
                for (int nb = 0; nb < 4; nb++)
                    mma_16x8x8(acc[mb][nb], af[mb], bf[nb]);
        }
        __syncthreads();
    }

    #pragma unroll
    for (int mb = 0; mb < 4; mb++) {
        int row = bm + wm * 64 + mb * 16 + gq;
        #pragma unroll
        for (int nb = 0; nb < 4; nb++) {
            int col = wn * 32 + nb * 8 + 2 * tig;
            float b0 = 0.f, b1 = 0.f;
            if (epi_mode != 0) { b0 = bias[col]; b1 = bias[col + 1]; }
            float v0 = acc[mb][nb][0], v1 = acc[mb][nb][1];
            float v2 = acc[mb][nb][2], v3 = acc[mb][nb][3];
            if (epi_mode == 1) {
                v0 = 1.0f / (1.0f + __expf(-(v0 + b0)));
                v1 = 1.0f / (1.0f + __expf(-(v1 + b1)));
                v2 = 1.0f / (1.0f + __expf(-(v2 + b0)));
                v3 = 1.0f / (1.0f + __expf(-(v3 + b1)));
            } else if (epi_mode == 2) {
                v0 += b0; v1 += b1; v2 += b0; v3 += b1;
            }
            *(float2*)&Cout[(size_t)row * 256 + col]       = make_float2(v0, v1);
            *(float2*)&Cout[(size_t)(row + 8) * 256 + col] = make_float2(v2, v3);
        }
    }
}

// ============================ Attention (tf32 mma.sync, 512 thr) ============================
// 1 CTA (512 thr, 16 warps) per (l, h). K,V^T tf32-staged once; 2 s-tiles of 128.
// QK^T: warps 2x8, warp-tile 64x32 (same pattern as gemm_mma).
// Softmax: 8 rows/warp. PV: warps (rg, nh), warp-tile 16x16.
#define AKST 36                         // k_sm/q_sm stride (36 mod 32 = 4 -> conflict-free)
#define AVST 260                        // v^T stride
#define ASST 260                        // score stride
#define AK_F (256 * AKST)               // 9216
#define AV_F (32 * AVST)                // 8320
#define AQ_F (128 * AKST)               // 4608
#define ASF  (128 * ASST)               // 33280
#define ATTN_SMEM ((AK_F + AV_F + AQ_F + ASF + 128) * 4)   // 222208 bytes

__global__ __launch_bounds__(512, 1) void attn_mma() {
    extern __shared__ float sm[];
    float* k_sm = sm;                   // [256][36]  K, row=t, col=c (tf32)
    float* v_sm = k_sm + AK_F;          // [32][260]  V^T, row=c, col=t (tf32)
    float* q_sm = v_sm + AV_F;          // [128][36]  Q tile (tf32)
    float* s_sm = q_sm + AQ_F;          // [128][260] scores / probs
    float* rsum = s_sm + ASF;           // [128] 1/rowsum

    int l = blockIdx.x >> 3;
    int h = blockIdx.x & 7;
    int tid = threadIdx.x;
    int wid = tid >> 5, lane = tid & 31;
    int gq = lane >> 2, tig = lane & 3;
    size_t hoff = (size_t)h * CDIM;

    // ---- stage K (256x32) and V^T (32x256), tf32 ----
    for (int i = tid; i < 2048; i += 512) {        // K: float4 granularity
        int t = i >> 3, c = (i & 7) << 2;
        float4 d = *(const float4*)&g_k[((size_t)(t * LRES + l)) * HC + hoff + c];
        float4 r = make_float4(tf32r(d.x), tf32r(d.y), tf32r(d.z), tf32r(d.w));
        *(float4*)&k_sm[t * AKST + c] = r;
    }
    for (int i = tid; i < 8192; i += 512) {        // V transpose (scalar)
        int t = i >> 5, c = i & 31;
        v_sm[c * AVST + t] = tf32r(g_v[((size_t)(t * LRES + l)) * HC + hoff + c]);
    }
    __syncthreads();

    for (int st = 0; st < 2; st++) {
        int sbase = st * 128;

        // ---- stage Q tile (128x32 = 1024 float4, 8 float4 per row), tf32 ----
        for (int i = tid; i < 1024; i += 512) {
            int r = i >> 3, c = (i & 7) << 2;
            float4 d = *(const float4*)&g_q[((size_t)((sbase + r) * LRES + l)) * HC + hoff + c];
            float4 v = make_float4(tf32r(d.x), tf32r(d.y), tf32r(d.z), tf32r(d.w));
            *(float4*)&q_sm[r * AKST + c] = v;
        }
        __syncthreads();

        // ---- QK^T: S[128,256] = Q[128,32] @ K^T; warps 2x8, tile 64x32 ----
        {
            int wm = wid >> 3, wn = wid & 7;
            float acc[4][4][4];
            #pragma unroll
            for (int i = 0; i < 4; i++)
                #pragma unroll
                for (int j = 0; j < 4; j++)
                    #pragma unroll
                    for (int z = 0; z < 4; z++) acc[i][j][z] = 0.0f;

            #pragma unroll
            for (int kk = 0; kk < 4; kk++) {
                int k0 = kk * 8;
                uint32_t af[4][4], bf[4][2];
                #pragma unroll
                for (int mb = 0; mb < 4; mb++) {
                    int r0 = wm * 64 + mb * 16 + gq;
                    af[mb][0] = __float_as_uint(q_sm[r0 * AKST + k0 + tig]);
                    af[mb][1] = __float_as_uint(q_sm[(r0 + 8) * AKST + k0 + tig]);
                    af[mb][2] = __float_as_uint(q_sm[r0 * AKST + k0 + tig + 4]);
                    af[mb][3] = __float_as_uint(q_sm[(r0 + 8) * AKST + k0 + tig + 4]);
                }
                #pragma unroll
                for (int nb = 0; nb < 4; nb++) {
                    int n0 = wn * 32 + nb * 8 + gq;
                    bf[nb][0] = __float_as_uint(k_sm[n0 * AKST + k0 + tig]);
                    bf[nb][1] = __float_as_uint(k_sm[n0 * AKST + k0 + tig + 4]);
                }
                #pragma unroll
                for (int mb = 0; mb < 4; mb++)
                    #pragma unroll
                    for (int nb = 0; nb < 4; nb++)
                        mma_16x8x8(acc[mb][nb], af[mb], bf[nb]);
            }
            // write scaled scores to s_sm
            #pragma unroll
            for (int mb = 0; mb < 4; mb++) {
                int row = wm * 64 + mb * 16 + gq;
                #pragma unroll
                for (int nb = 0; nb < 4; nb++) {
                    int col = wn * 32 + nb * 8 + 2 * tig;
                    *(float2*)&s_sm[row * ASST + col] =
                        make_float2(acc[mb][nb][0] * SQC, acc[mb][nb][1] * SQC);
                    *(float2*)&s_sm[(row + 8) * ASST + col] =
                        make_float2(acc[mb][nb][2] * SQC, acc[mb][nb][3] * SQC);
                }
            }
        }
        __syncthreads();

        // ---- softmax: warp wid owns rows wid*8 .. +7 ----
        for (int rr = 0; rr < 8; rr++) {
            int row = wid * 8 + rr;
            float vv[8];
            #pragma unroll
            for (int i = 0; i < 8; i++) vv[i] = s_sm[row * ASST + i * 32 + lane];
            float mx = vv[0];
            #pragma unroll
            for (int i = 1; i < 8; i++) mx = fmaxf(mx, vv[i]);
            #pragma unroll
            for (int o = 16; o; o >>= 1)
                mx = fmaxf(mx, __shfl_xor_sync(0xffffffffu, mx, o));
            float sum = 0.0f;
            #pragma unroll
            for (int i = 0; i < 8; i++) { vv[i] = __expf(vv[i] - mx); sum += vv[i]; }
            #pragma unroll
            for (int o = 16; o; o >>= 1)
                sum += __shfl_xor_sync(0xffffffffu, sum, o);
            #pragma unroll
            for (int i = 0; i < 8; i++)
                s_sm[row * ASST + i * 32 + lane] = tf32r(vv[i]);
            if (lane == 0) rsum[row] = 1.0f / sum;
        }
        __syncthreads();

        // ---- PV: O[128,32] = P[128,256] @ V; warp (rg, nh), tile 16x16 ----
        {
            int rg = wid >> 1, nh = wid & 1;
            float acc2[2][4];
            #pragma unroll
            for (int j = 0; j < 2; j++)
                #pragma unroll
                for (int z = 0; z < 4; z++) acc2[j][z] = 0.0f;

            int r0 = rg * 16 + gq;
            #pragma unroll
            for (int kk = 0; kk < 32; kk++) {
                int k0 = kk * 8;
                uint32_t af[4], bf[2][2];
                af[0] = __float_as_uint(s_sm[r0 * ASST + k0 + tig]);
                af[1] = __float_as_uint(s_sm[(r0 + 8) * ASST + k0 + tig]);
                af[2] = __float_as_uint(s_sm[r0 * ASST + k0 + tig + 4]);
                af[3] = __float_as_uint(s_sm[(r0 + 8) * ASST + k0 + tig + 4]);
                #pragma unroll
                for (int nb = 0; nb < 2; nb++) {
                    int n0 = nh * 16 + nb * 8 + gq;
                    bf[nb][0] = __float_as_uint(v_sm[n0 * AVST + k0 + tig]);
                    bf[nb][1] = __float_as_uint(v_sm[n0 * AVST + k0 + tig + 4]);
                }
                #pragma unroll
                for (int nb = 0; nb < 2; nb++)
                    mma_16x8x8(acc2[nb], af, bf[nb]);
            }

            // epilogue: normalize, gate, store
            float ri0 = rsum[rg * 16 + gq];
            float ri1 = rsum[rg * 16 + gq + 8];
            int srow0 = sbase + rg * 16 + gq;
            #pragma unroll
            for (int nb = 0; nb < 2; nb++) {
                int col = nh * 16 + nb * 8 + 2 * tig;
                size_t o0 = ((size_t)(srow0 * LRES + l)) * HC + hoff + col;
                size_t o1 = ((size_t)((srow0 + 8) * LRES + l)) * HC + hoff + col;
                float2 gg0 = *(const float2*)&g_g[o0];
                float2 gg1 = *(const float2*)&g_g[o1];
                *(float2*)&g_o[o0] = make_float2(acc2[nb][0] * ri0 * gg0.x,
                                                 acc2[nb][1] * ri0 * gg0.y);
                *(float2*)&g_o[o1] = make_float2(acc2[nb][2] * ri1 * gg1.x,
                                                 acc2[nb][3] * ri1 * gg1.y);
            }
        }
        __syncthreads();   // protect q_sm/s_sm before next s-tile
    }
}

// ============================ launch ============================
extern "C" void kernel_launch(void* const* d_in, const int* in_sizes, int n_in,
                              void* d_out, int out_size) {
    (void)in_sizes; (void)n_in; (void)out_size;
    const float* m     = (const float*)d_in[0];
    const float* gamma = (const float*)d_in[1];
    const float* beta  = (const float*)d_in[2];
    const float* Wq    = (const float*)d_in[3];
    const float* Wk    = (const float*)d_in[4];
    const float* Wv    = (const float*)d_in[5];
    const float* Wg    = (const float*)d_in[6];
    const float* bg    = (const float*)d_in[7];
    const float* Wo    = (const float*)d_in[8];
    const float* bo    = (const float*)d_in[9];
    float* out = (float*)d_out;

    float *x, *q, *k, *v, *g, *o, *wt;
    cudaGetSymbolAddress((void**)&x, g_x);
    cudaGetSymbolAddress((void**)&q, g_q);
    cudaGetSymbolAddress((void**)&k, g_k);
    cudaGetSymbolAddress((void**)&v, g_v);
    cudaGetSymbolAddress((void**)&g, g_g);
    cudaGetSymbolAddress((void**)&o, g_o);
    cudaGetSymbolAddress((void**)&wt, g_wt);

    cudaFuncSetAttribute(gemm_mma, cudaFuncAttributeMaxDynamicSharedMemorySize,
                         MMA_SMEM);
    cudaFuncSetAttribute(attn_mma, cudaFuncAttributeMaxDynamicSharedMemorySize,
                         ATTN_SMEM);

    // 1) layernorm + weight transposes
    ln_kernel<<<NL, 64>>>(m, gamma, beta);
    dim3 trb(32, 8), trg(8, 8);
    tr_kernel<<<trg, trb>>>(Wq, wt + 0 * 65536);
    tr_kernel<<<trg, trb>>>(Wk, wt + 1 * 65536);
    tr_kernel<<<trg, trb>>>(Wv, wt + 2 * 65536);
    tr_kernel<<<trg, trb>>>(Wg, wt + 3 * 65536);
    tr_kernel<<<trg, trb>>>(Wo, wt + 4 * 65536);

    // 2) projections via tf32 mma.sync
    gemm_mma<<<NL / 128, 512, MMA_SMEM>>>(x, wt + 0 * 65536, nullptr, q, 0);
    gemm_mma<<<NL / 128, 512, MMA_SMEM>>>(x, wt + 1 * 65536, nullptr, k, 0);
    gemm_mma<<<NL / 128, 512, MMA_SMEM>>>(x, wt + 2 * 65536, nullptr, v, 0);
    gemm_mma<<<NL / 128, 512, MMA_SMEM>>>(x, wt + 3 * 65536, bg, g, 1);

    // 3) attention per (l, h) via tf32 mma.sync (512 threads)
    attn_mma<<<LRES * NHEAD, 512, ATTN_SMEM>>>();

    // 4) output projection + bias
    gemm_mma<<<NL / 128, 512, MMA_SMEM>>>(o, wt + 4 * 65536, bo, out, 2);
}

// round 16
// speedup vs baseline: 2.8875x; 1.0305x over previous
#include <cuda_runtime.h>
#include <math.h>
#include <stdint.h>

#define NSEQ  256
#define LRES  384
#define MDIM  256
#define NHEAD 8
#define CDIM  32
#define HC    256
#define NL    (NSEQ * LRES)            // 98304
#define SQC   0.17677669529663687f     // 1/sqrt(32)

typedef unsigned long long ull;

// -------- scratch (static device globals; no allocations allowed) --------
__device__ float g_x[(size_t)NL * MDIM];   // layernormed input (tf32-rounded)
__device__ float g_q[(size_t)NL * HC];     // tf32-rounded
__device__ float g_k[(size_t)NL * HC];     // tf32-rounded
__device__ float g_v[(size_t)NL * HC];     // tf32-rounded
__device__ float g_g[(size_t)NL * HC];     // sigmoid gate (full precision)
__device__ float g_o[(size_t)NL * HC];     // gated attention output (tf32-rounded)
__device__ float g_wt[5 * 256 * 256];      // transposed weights [n][k] (tf32-rounded)

// -------- tf32 helpers --------
__device__ __forceinline__ float tf32r(float f) {
    uint32_t u;
    asm("cvt.rna.tf32.f32 %0, %1;" : "=r"(u) : "f"(f));
    return __uint_as_float(u);
}
__device__ __forceinline__ void mma_16x8x8(float* c, const uint32_t* a, const uint32_t* b) {
    asm volatile(
        "mma.sync.aligned.m16n8k8.row.col.f32.tf32.tf32.f32 "
        "{%0,%1,%2,%3}, {%4,%5,%6,%7}, {%8,%9}, {%0,%1,%2,%3};"
        : "+f"(c[0]), "+f"(c[1]), "+f"(c[2]), "+f"(c[3])
        : "r"(a[0]), "r"(a[1]), "r"(a[2]), "r"(a[3]), "r"(b[0]), "r"(b[1]));
}
__device__ __forceinline__ uint32_t s2u(const void* p) {
    return (uint32_t)__cvta_generic_to_shared(p);
}
__device__ __forceinline__ void cp16(uint32_t saddr, const void* gaddr) {
    asm volatile("cp.async.ca.shared.global [%0], [%1], 16;"
                 :: "r"(saddr), "l"(gaddr) : "memory");
}

// ============================ LayerNorm (stores tf32-rounded x) ============================
__global__ void ln_kernel(const float* __restrict__ m,
                          const float* __restrict__ gamma,
                          const float* __restrict__ beta) {
    int row = blockIdx.x;
    const float4* mr = (const float4*)(m + (size_t)row * MDIM);
    float4* xr = (float4*)(g_x + (size_t)row * MDIM);
    int tid = threadIdx.x;

    float4 v = mr[tid];
    float s  = v.x + v.y + v.z + v.w;
    float ss = v.x * v.x + v.y * v.y + v.z * v.z + v.w * v.w;
    #pragma unroll
    for (int o = 16; o; o >>= 1) {
        s  += __shfl_xor_sync(0xffffffffu, s,  o);
        ss += __shfl_xor_sync(0xffffffffu, ss, o);
    }
    __shared__ float sh[4];
    if ((tid & 31) == 0) { sh[tid >> 5] = s; sh[2 + (tid >> 5)] = ss; }
    __syncthreads();
    s  = sh[0] + sh[1];
    ss = sh[2] + sh[3];
    float mu  = s * (1.0f / MDIM);
    float var = ss * (1.0f / MDIM) - mu * mu;
    float inv = rsqrtf(var + 1e-5f);

    float4 gm = ((const float4*)gamma)[tid];
    float4 bt = ((const float4*)beta)[tid];
    float4 r;
    r.x = tf32r((v.x - mu) * inv * gm.x + bt.x);
    r.y = tf32r((v.y - mu) * inv * gm.y + bt.y);
    r.z = tf32r((v.z - mu) * inv * gm.z + bt.z);
    r.w = tf32r((v.w - mu) * inv * gm.w + bt.w);
    xr[tid] = r;
}

// ============================ weight transpose (stores tf32-rounded) ============================
__global__ void tr_kernel(const float* __restrict__ W, float* __restrict__ Wt) {
    __shared__ float t[32][33];
    int bx = blockIdx.x * 32, by = blockIdx.y * 32;
    int x = threadIdx.x, y = threadIdx.y;
    #pragma unroll
    for (int i = 0; i < 32; i += 8)
        t[y + i][x] = W[(size_t)(by + y + i) * 256 + bx + x];
    __syncthreads();
    #pragma unroll
    for (int i = 0; i < 32; i += 8)
        Wt[(size_t)(bx + y + i) * 256 + by + x] = tf32r(t[x][y + i]);
}

// ============================ tf32 mma.sync GEMM (cp.async double-buffered) ============================
// C[M,256] = A[M,256] (row-major, pre-rounded) * Bt[256 n][256 k] (pre-rounded).
// fused=1: grid.y=4 selects {q,k,v,g}; epi: q/k/v store tf32r, g sigmoid+bias.
// fused=0: Wo gemm: Bt = WtAll+4*65536, C0 = out, epi add-bias.
#define AS_ST 68
#define AS_F  (128 * AS_ST)            // 8704 floats
#define BS_F  (256 * AS_ST)            // 17408 floats
#define STG_F (AS_F + BS_F)            // 26112 floats / stage
#define GEMM_SMEM (2 * STG_F * 4)      // 208896 bytes

__global__ __launch_bounds__(512, 1)
void gemm_cp(const float* __restrict__ A, const float* __restrict__ WtAll,
             const float* __restrict__ bias,
             float* __restrict__ C0, float* __restrict__ C1,
             float* __restrict__ C2, float* __restrict__ C3,
             int fused) {
    extern __shared__ float sh[];

    int which = fused ? blockIdx.y : 0;
    const float* Bt = WtAll + (size_t)(fused ? which : 4) * 65536;
    float* Cout = C0;
    if (fused) Cout = (which == 0) ? C0 : (which == 1) ? C1 : (which == 2) ? C2 : C3;
    int epi = fused ? ((which == 3) ? 1 : 0) : 2;   // 0: tf32r store, 1: sigmoid+bias, 2: +bias

    int tid = threadIdx.x;
    int wid = tid >> 5, lane = tid & 31;
    int gq = lane >> 2, tig = lane & 3;
    int wm = wid >> 3, wn = wid & 7;
    int bm = blockIdx.x * 128;

    float acc[4][4][4];
    #pragma unroll
    for (int i = 0; i < 4; i++)
        #pragma unroll
        for (int j = 0; j < 4; j++)
            #pragma unroll
            for (int z = 0; z < 4; z++) acc[i][j][z] = 0.0f;

    // stage issue: chunk kc -> stage buffer s
    auto issue = [&](int kc, int s) {
        float* sA = sh + s * STG_F;
        float* sB = sh + s * STG_F + AS_F;
        int k0g = kc * 64;
        #pragma unroll
        for (int j = 0; j < 4; j++) {
            int idx = j * 512 + tid;
            int r = idx >> 4, c = (idx & 15) << 2;
            cp16(s2u(&sA[r * AS_ST + c]), &A[(size_t)(bm + r) * 256 + k0g + c]);
        }
        #pragma unroll
        for (int j = 0; j < 8; j++) {
            int idx = j * 512 + tid;
            int n = idx >> 4, c = (idx & 15) << 2;
            cp16(s2u(&sB[n * AS_ST + c]), &Bt[(size_t)n * 256 + k0g + c]);
        }
        asm volatile("cp.async.commit_group;" ::: "memory");
    };

    issue(0, 0);
    issue(1, 1);

    for (int kc = 0; kc < 4; kc++) {
        int s = kc & 1;
        if (kc == 3) asm volatile("cp.async.wait_group 0;" ::: "memory");
        else         asm volatile("cp.async.wait_group 1;" ::: "memory");
        __syncthreads();

        float* As = sh + s * STG_F;
        float* Bs = sh + s * STG_F + AS_F;

        #pragma unroll
        for (int kk = 0; kk < 8; kk++) {
            int k0 = kk * 8;
            uint32_t af[4][4], bf[4][2];
            #pragma unroll
            for (int mb = 0; mb < 4; mb++) {
                int r0 = wm * 64 + mb * 16 + gq;
                af[mb][0] = __float_as_uint(As[r0 * AS_ST + k0 + tig]);
                af[mb][1] = __float_as_uint(As[(r0 + 8) * AS_ST + k0 + tig]);
                af[mb][2] = __float_as_uint(As[r0 * AS_ST + k0 + tig + 4]);
                af[mb][3] = __float_as_uint(As[(r0 + 8) * AS_ST + k0 + tig + 4]);
            }
            #pragma unroll
            for (int nb = 0; nb < 4; nb++) {
                int n0 = wn * 32 + nb * 8 + gq;
                bf[nb][0] = __float_as_uint(Bs[n0 * AS_ST + k0 + tig]);
                bf[nb][1] = __float_as_uint(Bs[n0 * AS_ST + k0 + tig + 4]);
            }
            #pragma unroll
            for (int mb = 0; mb < 4; mb++)
                #pragma unroll
                for (int nb = 0; nb < 4; nb++)
                    mma_16x8x8(acc[mb][nb], af[mb], bf[nb]);
        }
        __syncthreads();
        if (kc < 2) issue(kc + 2, s);
    }

    #pragma unroll
    for (int mb = 0; mb < 4; mb++) {
        int row = bm + wm * 64 + mb * 16 + gq;
        #pragma unroll
        for (int nb = 0; nb < 4; nb++) {
            int col = wn * 32 + nb * 8 + 2 * tig;
            float b0 = 0.f, b1 = 0.f;
            if (epi != 0) { b0 = bias[col]; b1 = bias[col + 1]; }
            float v0 = acc[mb][nb][0], v1 = acc[mb][nb][1];
            float v2 = acc[mb][nb][2], v3 = acc[mb][nb][3];
            if (epi == 1) {
                v0 = 1.0f / (1.0f + __expf(-(v0 + b0)));
                v1 = 1.0f / (1.0f + __expf(-(v1 + b1)));
                v2 = 1.0f / (1.0f + __expf(-(v2 + b0)));
                v3 = 1.0f / (1.0f + __expf(-(v3 + b1)));
            } else if (epi == 2) {
                v0 += b0; v1 += b1; v2 += b0; v3 += b1;
            } else {
                v0 = tf32r(v0); v1 = tf32r(v1); v2 = tf32r(v2); v3 = tf32r(v3);
            }
            *(float2*)&Cout[(size_t)row * 256 + col]       = make_float2(v0, v1);
            *(float2*)&Cout[(size_t)(row + 8) * 256 + col] = make_float2(v2, v3);
        }
    }
}

// ============================ Attention (tf32 mma.sync, 512 thr) ============================
// 1 CTA (512 thr, 16 warps) per (l, h). Inputs pre-rounded -> staging is pure copy.
#define AKST 36
#define AVST 260
#define ASST 260
#define AK_F (256 * AKST)               // 9216
#define AV_F (32 * AVST)                // 8320
#define AQ_F (128 * AKST)               // 4608
#define ASF  (128 * ASST)               // 33280
#define ATTN_SMEM ((AK_F + AV_F + AQ_F + ASF + 128) * 4)   // 222208 bytes

__global__ __launch_bounds__(512, 1) void attn_mma() {
    extern __shared__ float sm[];
    float* k_sm = sm;                   // [256][36]
    float* v_sm = k_sm + AK_F;          // [32][260]  V^T
    float* q_sm = v_sm + AV_F;          // [128][36]
    float* s_sm = q_sm + AQ_F;          // [128][260]
    float* rsum = s_sm + ASF;           // [128]

    int l = blockIdx.x >> 3;
    int h = blockIdx.x & 7;
    int tid = threadIdx.x;
    int wid = tid >> 5, lane = tid & 31;
    int gq = lane >> 2, tig = lane & 3;
    size_t hoff = (size_t)h * CDIM;

    // ---- stage K (256x32) and V^T (32x256) — raw copies (pre-rounded) ----
    for (int i = tid; i < 2048; i += 512) {
        int t = i >> 3, c = (i & 7) << 2;
        *(float4*)&k_sm[t * AKST + c] =
            *(const float4*)&g_k[((size_t)(t * LRES + l)) * HC + hoff + c];
    }
    for (int i = tid; i < 8192; i += 512) {
        int t = i >> 5, c = i & 31;
        v_sm[c * AVST + t] = g_v[((size_t)(t * LRES + l)) * HC + hoff + c];
    }
    __syncthreads();

    for (int st = 0; st < 2; st++) {
        int sbase = st * 128;

        for (int i = tid; i < 1024; i += 512) {
            int r = i >> 3, c = (i & 7) << 2;
            *(float4*)&q_sm[r * AKST + c] =
                *(const float4*)&g_q[((size_t)((sbase + r) * LRES + l)) * HC + hoff + c];
        }
        __syncthreads();

        // ---- QK^T: warps 2x8, tile 64x32 ----
        {
            int wm = wid >> 3, wn = wid & 7;
            float acc[4][4][4];
            #pragma unroll
            for (int i = 0; i < 4; i++)
                #pragma unroll
                for (int j = 0; j < 4; j++)
                    #pragma unroll
                    for (int z = 0; z < 4; z++) acc[i][j][z] = 0.0f;

            #pragma unroll
            for (int kk = 0; kk < 4; kk++) {
                int k0 = kk * 8;
                uint32_t af[4][4], bf[4][2];
                #pragma unroll
                for (int mb = 0; mb < 4; mb++) {
                    int r0 = wm * 64 + mb * 16 + gq;
                    af[mb][0] = __float_as_uint(q_sm[r0 * AKST + k0 + tig]);
                    af[mb][1] = __float_as_uint(q_sm[(r0 + 8) * AKST + k0 + tig]);
                    af[mb][2] = __float_as_uint(q_sm[r0 * AKST + k0 + tig + 4]);
                    af[mb][3] = __float_as_uint(q_sm[(r0 + 8) * AKST + k0 + tig + 4]);
                }
                #pragma unroll
                for (int nb = 0; nb < 4; nb++) {
                    int n0 = wn * 32 + nb * 8 + gq;
                    bf[nb][0] = __float_as_uint(k_sm[n0 * AKST + k0 + tig]);
                    bf[nb][1] = __float_as_uint(k_sm[n0 * AKST + k0 + tig + 4]);
                }
                #pragma unroll
                for (int mb = 0; mb < 4; mb++)
                    #pragma unroll
                    for (int nb = 0; nb < 4; nb++)
                        mma_16x8x8(acc[mb][nb], af[mb], bf[nb]);
            }
            #pragma unroll
            for (int mb = 0; mb < 4; mb++) {
                int row = wm * 64 + mb * 16 + gq;
                #pragma unroll
                for (int nb = 0; nb < 4; nb++) {
                    int col = wn * 32 + nb * 8 + 2 * tig;
                    *(float2*)&s_sm[row * ASST + col] =
                        make_float2(acc[mb][nb][0] * SQC, acc[mb][nb][1] * SQC);
                    *(float2*)&s_sm[(row + 8) * ASST + col] =
                        make_float2(acc[mb][nb][2] * SQC, acc[mb][nb][3] * SQC);
                }
            }
        }
        __syncthreads();

        // ---- softmax: 8 rows/warp ----
        for (int rr = 0; rr < 8; rr++) {
            int row = wid * 8 + rr;
            float vv[8];
            #pragma unroll
            for (int i = 0; i < 8; i++) vv[i] = s_sm[row * ASST + i * 32 + lane];
            float mx = vv[0];
            #pragma unroll
            for (int i = 1; i < 8; i++) mx = fmaxf(mx, vv[i]);
            #pragma unroll
            for (int o = 16; o; o >>= 1)
                mx = fmaxf(mx, __shfl_xor_sync(0xffffffffu, mx, o));
            float sum = 0.0f;
            #pragma unroll
            for (int i = 0; i < 8; i++) { vv[i] = __expf(vv[i] - mx); sum += vv[i]; }
            #pragma unroll
            for (int o = 16; o; o >>= 1)
                sum += __shfl_xor_sync(0xffffffffu, sum, o);
            #pragma unroll
            for (int i = 0; i < 8; i++)
                s_sm[row * ASST + i * 32 + lane] = tf32r(vv[i]);
            if (lane == 0) rsum[row] = 1.0f / sum;
        }
        __syncthreads();

        // ---- PV: warp (rg, nh), tile 16x16 ----
        {
            int rg = wid >> 1, nh = wid & 1;
            float acc2[2][4];
            #pragma unroll
            for (int j = 0; j < 2; j++)
                #pragma unroll
                for (int z = 0; z < 4; z++) acc2[j][z] = 0.0f;

            int r0 = rg * 16 + gq;
            #pragma unroll
            for (int kk = 0; kk < 32; kk++) {
                int k0 = kk * 8;
                uint32_t af[4], bf[2][2];
                af[0] = __float_as_uint(s_sm[r0 * ASST + k0 + tig]);
                af[1] = __float_as_uint(s_sm[(r0 + 8) * ASST + k0 + tig]);
                af[2] = __float_as_uint(s_sm[r0 * ASST + k0 + tig + 4]);
                af[3] = __float_as_uint(s_sm[(r0 + 8) * ASST + k0 + tig + 4]);
                #pragma unroll
                for (int nb = 0; nb < 2; nb++) {
                    int n0 = nh * 16 + nb * 8 + gq;
                    bf[nb][0] = __float_as_uint(v_sm[n0 * AVST + k0 + tig]);
                    bf[nb][1] = __float_as_uint(v_sm[n0 * AVST + k0 + tig + 4]);
                }
                #pragma unroll
                for (int nb = 0; nb < 2; nb++)
                    mma_16x8x8(acc2[nb], af, bf[nb]);
            }

            float ri0 = rsum[rg * 16 + gq];
            float ri1 = rsum[rg * 16 + gq + 8];
            int srow0 = sbase + rg * 16 + gq;
            #pragma unroll
            for (int nb = 0; nb < 2; nb++) {
                int col = nh * 16 + nb * 8 + 2 * tig;
                size_t o0 = ((size_t)(srow0 * LRES + l)) * HC + hoff + col;
                size_t o1 = ((size_t)((srow0 + 8) * LRES + l)) * HC + hoff + col;
                float2 gg0 = *(const float2*)&g_g[o0];
                float2 gg1 = *(const float2*)&g_g[o1];
                *(float2*)&g_o[o0] = make_float2(tf32r(acc2[nb][0] * ri0 * gg0.x),
                                                 tf32r(acc2[nb][1] * ri0 * gg0.y));
                *(float2*)&g_o[o1] = make_float2(tf32r(acc2[nb][2] * ri1 * gg1.x),
                                                 tf32r(acc2[nb][3] * ri1 * gg1.y));
            }
        }
        __syncthreads();
    }
}

// ============================ launch ============================
extern "C" void kernel_launch(void* const* d_in, const int* in_sizes, int n_in,
                              void* d_out, int out_size) {
    (void)in_sizes; (void)n_in; (void)out_size;
    const float* m     = (const float*)d_in[0];
    const float* gamma = (const float*)d_in[1];
    const float* beta  = (const float*)d_in[2];
    const float* Wq    = (const float*)d_in[3];
    const float* Wk    = (const float*)d_in[4];
    const float* Wv    = (const float*)d_in[5];
    const float* Wg    = (const float*)d_in[6];
    const float* bg    = (const float*)d_in[7];
    const float* Wo    = (const float*)d_in[8];
    const float* bo    = (const float*)d_in[9];
    float* out = (float*)d_out;

    float *x, *q, *k, *v, *g, *o, *wt;
    cudaGetSymbolAddress((void**)&x, g_x);
    cudaGetSymbolAddress((void**)&q, g_q);
    cudaGetSymbolAddress((void**)&k, g_k);
    cudaGetSymbolAddress((void**)&v, g_v);
    cudaGetSymbolAddress((void**)&g, g_g);
    cudaGetSymbolAddress((void**)&o, g_o);
    cudaGetSymbolAddress((void**)&wt, g_wt);

    cudaFuncSetAttribute(gemm_cp, cudaFuncAttributeMaxDynamicSharedMemorySize,
                         GEMM_SMEM);
    cudaFuncSetAttribute(attn_mma, cudaFuncAttributeMaxDynamicSharedMemorySize,
                         ATTN_SMEM);

    // 1) layernorm + weight transposes (all outputs tf32-pre-rounded)
    ln_kernel<<<NL, 64>>>(m, gamma, beta);
    dim3 trb(32, 8), trg(8, 8);
    tr_kernel<<<trg, trb>>>(Wq, wt + 0 * 65536);
    tr_kernel<<<trg, trb>>>(Wk, wt + 1 * 65536);
    tr_kernel<<<trg, trb>>>(Wv, wt + 2 * 65536);
    tr_kernel<<<trg, trb>>>(Wg, wt + 3 * 65536);
    tr_kernel<<<trg, trb>>>(Wo, wt + 4 * 65536);

    // 2) fused Q/K/V/G projections (one launch, grid.y selects output)
    gemm_cp<<<dim3(NL / 128, 4), 512, GEMM_SMEM>>>(x, wt, bg, q, k, v, g, 1);

    // 3) attention per (l, h)
    attn_mma<<<LRES * NHEAD, 512, ATTN_SMEM>>>();

    // 4) output projection + bias
    gemm_cp<<<dim3(NL / 128, 1), 512, GEMM_SMEM>>>(o, wt, bo, out, nullptr, nullptr, nullptr, 0);
}

// round 17
// speedup vs baseline: 3.7514x; 1.2992x over previous
#include <cuda_runtime.h>
#include <cuda_fp16.h>
#include <math.h>
#include <stdint.h>

#define NSEQ  256
#define LRES  384
#define MDIM  256
#define NHEAD 8
#define CDIM  32
#define HC    256
#define NL    (NSEQ * LRES)            // 98304
#define SQC   0.17677669529663687f     // 1/sqrt(32)

// -------- scratch (static device globals; no allocations allowed) --------
__device__ float  g_x[(size_t)NL * MDIM];   // layernormed input (tf32-rounded)
__device__ __half g_qh[(size_t)NL * HC];    // half q
__device__ __half g_kh[(size_t)NL * HC];    // half k
__device__ __half g_vh[(size_t)NL * HC];    // half v
__device__ float  g_g[(size_t)NL * HC];     // sigmoid gate (full precision)
__device__ float  g_o[(size_t)NL * HC];     // gated attention output (tf32-rounded)
__device__ float  g_wt[5 * 256 * 256];      // transposed weights [n][k] (tf32-rounded)

// -------- helpers --------
__device__ __forceinline__ float tf32r(float f) {
    uint32_t u;
    asm("cvt.rna.tf32.f32 %0, %1;" : "=r"(u) : "f"(f));
    return __uint_as_float(u);
}
__device__ __forceinline__ void mma_16x8x8(float* c, const uint32_t* a, const uint32_t* b) {
    asm volatile(
        "mma.sync.aligned.m16n8k8.row.col.f32.tf32.tf32.f32 "
        "{%0,%1,%2,%3}, {%4,%5,%6,%7}, {%8,%9}, {%0,%1,%2,%3};"
        : "+f"(c[0]), "+f"(c[1]), "+f"(c[2]), "+f"(c[3])
        : "r"(a[0]), "r"(a[1]), "r"(a[2]), "r"(a[3]), "r"(b[0]), "r"(b[1]));
}
__device__ __forceinline__ void mma_f16(float* c, const uint32_t* a, const uint32_t* b) {
    asm volatile(
        "mma.sync.aligned.m16n8k16.row.col.f32.f16.f16.f32 "
        "{%0,%1,%2,%3}, {%4,%5,%6,%7}, {%8,%9}, {%0,%1,%2,%3};"
        : "+f"(c[0]), "+f"(c[1]), "+f"(c[2]), "+f"(c[3])
        : "r"(a[0]), "r"(a[1]), "r"(a[2]), "r"(a[3]), "r"(b[0]), "r"(b[1]));
}
__device__ __forceinline__ uint32_t s2u(const void* p) {
    return (uint32_t)__cvta_generic_to_shared(p);
}
__device__ __forceinline__ void cp16(uint32_t saddr, const void* gaddr) {
    asm volatile("cp.async.ca.shared.global [%0], [%1], 16;"
                 :: "r"(saddr), "l"(gaddr) : "memory");
}
__device__ __forceinline__ uint32_t pack2(float a, float b) {
    __half2 h = __floats2half2_rn(a, b);
    return *(uint32_t*)&h;
}

// ============================ LayerNorm (stores tf32-rounded x) ============================
__global__ void ln_kernel(const float* __restrict__ m,
                          const float* __restrict__ gamma,
                          const float* __restrict__ beta) {
    int row = blockIdx.x;
    const float4* mr = (const float4*)(m + (size_t)row * MDIM);
    float4* xr = (float4*)(g_x + (size_t)row * MDIM);
    int tid = threadIdx.x;

    float4 v = mr[tid];
    float s  = v.x + v.y + v.z + v.w;
    float ss = v.x * v.x + v.y * v.y + v.z * v.z + v.w * v.w;
    #pragma unroll
    for (int o = 16; o; o >>= 1) {
        s  += __shfl_xor_sync(0xffffffffu, s,  o);
        ss += __shfl_xor_sync(0xffffffffu, ss, o);
    }
    __shared__ float sh[4];
    if ((tid & 31) == 0) { sh[tid >> 5] = s; sh[2 + (tid >> 5)] = ss; }
    __syncthreads();
    s  = sh[0] + sh[1];
    ss = sh[2] + sh[3];
    float mu  = s * (1.0f / MDIM);
    float var = ss * (1.0f / MDIM) - mu * mu;
    float inv = rsqrtf(var + 1e-5f);

    float4 gm = ((const float4*)gamma)[tid];
    float4 bt = ((const float4*)beta)[tid];
    float4 r;
    r.x = tf32r((v.x - mu) * inv * gm.x + bt.x);
    r.y = tf32r((v.y - mu) * inv * gm.y + bt.y);
    r.z = tf32r((v.z - mu) * inv * gm.z + bt.z);
    r.w = tf32r((v.w - mu) * inv * gm.w + bt.w);
    xr[tid] = r;
}

// ============================ weight transpose (stores tf32-rounded) ============================
__global__ void tr_kernel(const float* __restrict__ W, float* __restrict__ Wt) {
    __shared__ float t[32][33];
    int bx = blockIdx.x * 32, by = blockIdx.y * 32;
    int x = threadIdx.x, y = threadIdx.y;
    #pragma unroll
    for (int i = 0; i < 32; i += 8)
        t[y + i][x] = W[(size_t)(by + y + i) * 256 + bx + x];
    __syncthreads();
    #pragma unroll
    for (int i = 0; i < 32; i += 8)
        Wt[(size_t)(bx + y + i) * 256 + by + x] = tf32r(t[x][y + i]);
}

// ============================ tf32 mma.sync GEMM (cp.async double-buffered) ============================
// fused=1: grid.y=4 selects {q,k,v -> half2 out; g -> sigmoid f32}.
// fused=0: Wo gemm: C0 = out (f32), epi add-bias.
#define AS_ST 68
#define AS_F  (128 * AS_ST)
#define BS_F  (256 * AS_ST)
#define STG_F (AS_F + BS_F)
#define GEMM_SMEM (2 * STG_F * 4)      // 208896 bytes

__global__ __launch_bounds__(512, 1)
void gemm_cp(const float* __restrict__ A, const float* __restrict__ WtAll,
             const float* __restrict__ bias,
             void* __restrict__ C0, void* __restrict__ C1,
             void* __restrict__ C2, void* __restrict__ C3,
             int fused) {
    extern __shared__ float sh[];

    int which = fused ? blockIdx.y : 0;
    const float* Bt = WtAll + (size_t)(fused ? which : 4) * 65536;
    void* Cout = C0;
    if (fused) Cout = (which == 0) ? C0 : (which == 1) ? C1 : (which == 2) ? C2 : C3;
    int epi = fused ? ((which == 3) ? 1 : 0) : 2;   // 0: half2 store, 1: sigmoid+bias f32, 2: +bias f32

    int tid = threadIdx.x;
    int wid = tid >> 5, lane = tid & 31;
    int gq = lane >> 2, tig = lane & 3;
    int wm = wid >> 3, wn = wid & 7;
    int bm = blockIdx.x * 128;

    float acc[4][4][4];
    #pragma unroll
    for (int i = 0; i < 4; i++)
        #pragma unroll
        for (int j = 0; j < 4; j++)
            #pragma unroll
            for (int z = 0; z < 4; z++) acc[i][j][z] = 0.0f;

    auto issue = [&](int kc, int s) {
        float* sA = sh + s * STG_F;
        float* sB = sh + s * STG_F + AS_F;
        int k0g = kc * 64;
        #pragma unroll
        for (int j = 0; j < 4; j++) {
            int idx = j * 512 + tid;
            int r = idx >> 4, c = (idx & 15) << 2;
            cp16(s2u(&sA[r * AS_ST + c]), &A[(size_t)(bm + r) * 256 + k0g + c]);
        }
        #pragma unroll
        for (int j = 0; j < 8; j++) {
            int idx = j * 512 + tid;
            int n = idx >> 4, c = (idx & 15) << 2;
            cp16(s2u(&sB[n * AS_ST + c]), &Bt[(size_t)n * 256 + k0g + c]);
        }
        asm volatile("cp.async.commit_group;" ::: "memory");
    };

    issue(0, 0);
    issue(1, 1);

    for (int kc = 0; kc < 4; kc++) {
        int s = kc & 1;
        if (kc == 3) asm volatile("cp.async.wait_group 0;" ::: "memory");
        else         asm volatile("cp.async.wait_group 1;" ::: "memory");
        __syncthreads();

        float* As = sh + s * STG_F;
        float* Bs = sh + s * STG_F + AS_F;

        #pragma unroll
        for (int kk = 0; kk < 8; kk++) {
            int k0 = kk * 8;
            uint32_t af[4][4], bf[4][2];
            #pragma unroll
            for (int mb = 0; mb < 4; mb++) {
                int r0 = wm * 64 + mb * 16 + gq;
                af[mb][0] = __float_as_uint(As[r0 * AS_ST + k0 + tig]);
                af[mb][1] = __float_as_uint(As[(r0 + 8) * AS_ST + k0 + tig]);
                af[mb][2] = __float_as_uint(As[r0 * AS_ST + k0 + tig + 4]);
                af[mb][3] = __float_as_uint(As[(r0 + 8) * AS_ST + k0 + tig + 4]);
            }
            #pragma unroll
            for (int nb = 0; nb < 4; nb++) {
                int n0 = wn * 32 + nb * 8 + gq;
                bf[nb][0] = __float_as_uint(Bs[n0 * AS_ST + k0 + tig]);
                bf[nb][1] = __float_as_uint(Bs[n0 * AS_ST + k0 + tig + 4]);
            }
            #pragma unroll
            for (int mb = 0; mb < 4; mb++)
                #pragma unroll
                for (int nb = 0; nb < 4; nb++)
                    mma_16x8x8(acc[mb][nb], af[mb], bf[nb]);
        }
        __syncthreads();
        if (kc < 2) issue(kc + 2, s);
    }

    #pragma unroll
    for (int mb = 0; mb < 4; mb++) {
        int row = bm + wm * 64 + mb * 16 + gq;
        #pragma unroll
        for (int nb = 0; nb < 4; nb++) {
            int col = wn * 32 + nb * 8 + 2 * tig;
            float v0 = acc[mb][nb][0], v1 = acc[mb][nb][1];
            float v2 = acc[mb][nb][2], v3 = acc[mb][nb][3];
            if (epi == 0) {
                uint32_t* dst = (uint32_t*)Cout;
                dst[((size_t)row * 256 + col) >> 1]       = pack2(v0, v1);
                dst[((size_t)(row + 8) * 256 + col) >> 1] = pack2(v2, v3);
            } else {
                float b0 = bias[col], b1 = bias[col + 1];
                if (epi == 1) {
                    v0 = 1.0f / (1.0f + __expf(-(v0 + b0)));
                    v1 = 1.0f / (1.0f + __expf(-(v1 + b1)));
                    v2 = 1.0f / (1.0f + __expf(-(v2 + b0)));
                    v3 = 1.0f / (1.0f + __expf(-(v3 + b1)));
                } else {
                    v0 += b0; v1 += b1; v2 += b0; v3 += b1;
                }
                float* dst = (float*)Cout;
                *(float2*)&dst[(size_t)row * 256 + col]       = make_float2(v0, v1);
                *(float2*)&dst[(size_t)(row + 8) * 256 + col] = make_float2(v2, v3);
            }
        }
    }
}

// ============================ Attention (fp16 mma.sync, fragment-packed smem) ============================
// 1 CTA (512 thr, 16 warps) per (l, h). Fragment layouts (uint32 = half2):
//  qhf[8rg][2kk][8gq][4tig][4j]   A-frag Q (8KB)
//  khf[32ng][2kk][8gq][4tig][2j]  B-frag K (16KB)
//  vhf[4ng][16kk][8gq][4tig][2j]  B-frag V (16KB)
//  phf[8rg][16kk][8gq][4tig][4j]  A-frag P half2 (64KB)
#define ATTN_SMEM 115712

__global__ __launch_bounds__(512, 1) void attn_mma() {
    extern __shared__ uint32_t usm[];
    uint32_t* qhf = usm;                    // 2048
    uint32_t* khf = qhf + 2048;             // 4096
    uint32_t* vhf = khf + 4096;             // 4096
    uint32_t* phf = vhf + 4096;             // 16384
    float* redmax = (float*)(phf + 16384);  // 1024
    float* redsum = redmax + 1024;          // 1024
    float* rmax   = redsum + 1024;          // 128
    float* rsum   = rmax + 128;             // 128

    int l = blockIdx.x >> 3;
    int h = blockIdx.x & 7;
    int tid = threadIdx.x;
    int wid = tid >> 5, lane = tid & 31;
    int gq = lane >> 2, tig = lane & 3;
    size_t hoff = (size_t)h * CDIM;

    // ---- stage K fragments (1024 uint4 reads of 4 half2 each) ----
    for (int i = tid; i < 1024; i += 512) {
        int t = i >> 2, c8 = (i & 3) << 3;
        const uint4* src = (const uint4*)(g_kh + ((size_t)(t * LRES + l)) * HC + hoff + c8);
        uint4 d = *src;
        uint32_t u[4] = { d.x, d.y, d.z, d.w };
        int ng = t >> 3, g8 = t & 7;
        #pragma unroll
        for (int p = 0; p < 4; p++) {
            int c = c8 + 2 * p;
            int kk = c >> 4, rem = c & 15, jj = rem >> 3, tg = (rem & 7) >> 1;
            khf[(((ng * 2 + kk) * 8 + g8) * 4 + tg) * 2 + jj] = u[p];
        }
    }
    // ---- stage V fragments (scattered half reads, packed over t) ----
    for (int p = tid; p < 4096; p += 512) {
        int jj = p & 1, tg = (p >> 1) & 3, g8 = (p >> 3) & 7;
        int kk = (p >> 6) & 15, ng = (p >> 10) & 3;
        int t0 = kk * 16 + 2 * tg + 8 * jj;
        int c = ng * 8 + g8;
        __half lo = g_vh[((size_t)(t0 * LRES + l)) * HC + hoff + c];
        __half hi = g_vh[((size_t)((t0 + 1) * LRES + l)) * HC + hoff + c];
        __half2 hh = __halves2half2(lo, hi);
        vhf[p] = *(uint32_t*)&hh;
    }
    __syncthreads();

    for (int st = 0; st < 2; st++) {
        int sbase = st * 128;

        // ---- stage Q tile fragments (512 uint4 reads) ----
        for (int i = tid; i < 512; i += 512) {
            int r = i >> 2, c8 = (i & 3) << 3;
            const uint4* src = (const uint4*)(g_qh + ((size_t)((sbase + r) * LRES + l)) * HC + hoff + c8);
            uint4 d = *src;
            uint32_t u[4] = { d.x, d.y, d.z, d.w };
            int rg = r >> 4, rh = (r >> 3) & 1, g8 = r & 7;
            #pragma unroll
            for (int p = 0; p < 4; p++) {
                int c = c8 + 2 * p;
                int kk = c >> 4, rem = c & 15, kh = rem >> 3, tg = (rem & 7) >> 1;
                qhf[(((rg * 2 + kk) * 8 + g8) * 4 + tg) * 4 + kh * 2 + rh] = u[p];
            }
        }
        __syncthreads();

        // ---- QK^T: warps 2x8, warp-tile 64x32; fp16 mma K=16 ----
        int wm = wid >> 3, wn = wid & 7;
        float c[4][4][4];
        #pragma unroll
        for (int i = 0; i < 4; i++)
            #pragma unroll
            for (int j = 0; j < 4; j++)
                #pragma unroll
                for (int z = 0; z < 4; z++) c[i][j][z] = 0.0f;

        #pragma unroll
        for (int kk = 0; kk < 2; kk++) {
            uint32_t af[4][4], bf[4][2];
            #pragma unroll
            for (int mb = 0; mb < 4; mb++) {
                uint4 A = *(uint4*)&qhf[(((wm * 4 + mb) * 2 + kk) * 8 + gq) * 16 + tig * 4];
                af[mb][0] = A.x; af[mb][1] = A.y; af[mb][2] = A.z; af[mb][3] = A.w;
            }
            #pragma unroll
            for (int nb = 0; nb < 4; nb++) {
                uint2 B = *(uint2*)&khf[(((wn * 4 + nb) * 2 + kk) * 8 + gq) * 8 + tig * 2];
                bf[nb][0] = B.x; bf[nb][1] = B.y;
            }
            #pragma unroll
            for (int mb = 0; mb < 4; mb++)
                #pragma unroll
                for (int nb = 0; nb < 4; nb++)
                    mma_f16(c[mb][nb], af[mb], bf[nb]);
        }
        // scale
        #pragma unroll
        for (int mb = 0; mb < 4; mb++)
            #pragma unroll
            for (int nb = 0; nb < 4; nb++)
                #pragma unroll
                for (int z = 0; z < 4; z++) c[mb][nb][z] *= SQC;

        // ---- partial row max -> redmax[row][wn] ----
        #pragma unroll
        for (int mb = 0; mb < 4; mb++) {
            #pragma unroll
            for (int rh = 0; rh < 2; rh++) {
                float pm = -1e30f;
                #pragma unroll
                for (int nb = 0; nb < 4; nb++)
                    pm = fmaxf(pm, fmaxf(c[mb][nb][2 * rh], c[mb][nb][2 * rh + 1]));
                pm = fmaxf(pm, __shfl_xor_sync(0xffffffffu, pm, 1));
                pm = fmaxf(pm, __shfl_xor_sync(0xffffffffu, pm, 2));
                if (tig == 0)
                    redmax[(wm * 64 + mb * 16 + rh * 8 + gq) * 8 + wn] = pm;
            }
        }
        __syncthreads();

        // ---- rmax reduce: warp wid owns rows wid*8..+7 ----
        #pragma unroll
        for (int rr = 0; rr < 8; rr++) {
            int row = wid * 8 + rr;
            float v = (lane < 8) ? redmax[row * 8 + lane] : -1e30f;
            v = fmaxf(v, __shfl_xor_sync(0xffffffffu, v, 4));
            v = fmaxf(v, __shfl_xor_sync(0xffffffffu, v, 2));
            v = fmaxf(v, __shfl_xor_sync(0xffffffffu, v, 1));
            if (lane == 0) rmax[row] = v;
        }
        __syncthreads();

        // ---- exp, write P fragments (half2), partial sums ----
        #pragma unroll
        for (int mb = 0; mb < 4; mb++) {
            int row0 = wm * 64 + mb * 16 + gq;
            float mx0 = rmax[row0], mx1 = rmax[row0 + 8];
            float s0 = 0.0f, s1 = 0.0f;
            int rg = wm * 4 + mb;
            #pragma unroll
            for (int nb = 0; nb < 4; nb++) {
                float e0 = __expf(c[mb][nb][0] - mx0);
                float e1 = __expf(c[mb][nb][1] - mx0);
                float e2 = __expf(c[mb][nb][2] - mx1);
                float e3 = __expf(c[mb][nb][3] - mx1);
                s0 += e0 + e1; s1 += e2 + e3;
                int kkp = wn * 2 + (nb >> 1), kh = nb & 1;
                uint2 pk = make_uint2(pack2(e0, e1), pack2(e2, e3));
                *(uint2*)&phf[((rg * 16 + kkp) * 8 + gq) * 16 + tig * 4 + kh * 2] = pk;
            }
            s0 += __shfl_xor_sync(0xffffffffu, s0, 1);
            s0 += __shfl_xor_sync(0xffffffffu, s0, 2);
            s1 += __shfl_xor_sync(0xffffffffu, s1, 1);
            s1 += __shfl_xor_sync(0xffffffffu, s1, 2);
            if (tig == 0) {
                redsum[row0 * 8 + wn] = s0;
                redsum[(row0 + 8) * 8 + wn] = s1;
            }
        }
        __syncthreads();

        // ---- rsum reduce (stores 1/sum) ----
        #pragma unroll
        for (int rr = 0; rr < 8; rr++) {
            int row = wid * 8 + rr;
            float v = (lane < 8) ? redsum[row * 8 + lane] : 0.0f;
            v += __shfl_xor_sync(0xffffffffu, v, 4);
            v += __shfl_xor_sync(0xffffffffu, v, 2);
            v += __shfl_xor_sync(0xffffffffu, v, 1);
            if (lane == 0) rsum[row] = 1.0f / v;
        }
        __syncthreads();

        // ---- PV: warp (rg, nh), tile 16x16, fp16 mma over 16 k-steps ----
        {
            int rg = wid >> 1, nh = wid & 1;
            float o2[2][4];
            #pragma unroll
            for (int j = 0; j < 2; j++)
                #pragma unroll
                for (int z = 0; z < 4; z++) o2[j][z] = 0.0f;

            #pragma unroll
            for (int kk = 0; kk < 16; kk++) {
                uint4 A = *(uint4*)&phf[((rg * 16 + kk) * 8 + gq) * 16 + tig * 4];
                uint32_t af[4] = { A.x, A.y, A.z, A.w };
                #pragma unroll
                for (int nb = 0; nb < 2; nb++) {
                    uint2 B = *(uint2*)&vhf[(((nh * 2 + nb) * 16 + kk) * 8 + gq) * 8 + tig * 2];
                    uint32_t bf[2] = { B.x, B.y };
                    mma_f16(o2[nb], af, bf);
                }
            }

            float ri0 = rsum[rg * 16 + gq];
            float ri1 = rsum[rg * 16 + gq + 8];
            int srow0 = sbase + rg * 16 + gq;
            #pragma unroll
            for (int nb = 0; nb < 2; nb++) {
                int col = nh * 16 + nb * 8 + 2 * tig;
                size_t o0 = ((size_t)(srow0 * LRES + l)) * HC + hoff + col;
                size_t o1 = ((size_t)((srow0 + 8) * LRES + l)) * HC + hoff + col;
                float2 gg0 = *(const float2*)&g_g[o0];
                float2 gg1 = *(const float2*)&g_g[o1];
                *(float2*)&g_o[o0] = make_float2(tf32r(o2[nb][0] * ri0 * gg0.x),
                                                 tf32r(o2[nb][1] * ri0 * gg0.y));
                *(float2*)&g_o[o1] = make_float2(tf32r(o2[nb][2] * ri1 * gg1.x),
                                                 tf32r(o2[nb][3] * ri1 * gg1.y));
            }
        }
        __syncthreads();
    }
}

// ============================ launch ============================
extern "C" void kernel_launch(void* const* d_in, const int* in_sizes, int n_in,
                              void* d_out, int out_size) {
    (void)in_sizes; (void)n_in; (void)out_size;
    const float* m     = (const float*)d_in[0];
    const float* gamma = (const float*)d_in[1];
    const float* beta  = (const float*)d_in[2];
    const float* Wq    = (const float*)d_in[3];
    const float* Wk    = (const float*)d_in[4];
    const float* Wv    = (const float*)d_in[5];
    const float* Wg    = (const float*)d_in[6];
    const float* bg    = (const float*)d_in[7];
    const float* Wo    = (const float*)d_in[8];
    const float* bo    = (const float*)d_in[9];
    float* out = (float*)d_out;

    float *x, *g, *o, *wt;
    __half *qh, *kh, *vh;
    cudaGetSymbolAddress((void**)&x,  g_x);
    cudaGetSymbolAddress((void**)&qh, g_qh);
    cudaGetSymbolAddress((void**)&kh, g_kh);
    cudaGetSymbolAddress((void**)&vh, g_vh);
    cudaGetSymbolAddress((void**)&g,  g_g);
    cudaGetSymbolAddress((void**)&o,  g_o);
    cudaGetSymbolAddress((void**)&wt, g_wt);

    cudaFuncSetAttribute(gemm_cp, cudaFuncAttributeMaxDynamicSharedMemorySize,
                         GEMM_SMEM);
    cudaFuncSetAttribute(attn_mma, cudaFuncAttributeMaxDynamicSharedMemorySize,
                         ATTN_SMEM);

    // 1) layernorm + weight transposes (tf32 pre-rounded)
    ln_kernel<<<NL, 64>>>(m, gamma, beta);
    dim3 trb(32, 8), trg(8, 8);
    tr_kernel<<<trg, trb>>>(Wq, wt + 0 * 65536);
    tr_kernel<<<trg, trb>>>(Wk, wt + 1 * 65536);
    tr_kernel<<<trg, trb>>>(Wv, wt + 2 * 65536);
    tr_kernel<<<trg, trb>>>(Wg, wt + 3 * 65536);
    tr_kernel<<<trg, trb>>>(Wo, wt + 4 * 65536);

    // 2) fused Q/K/V/G projections (q,k,v -> half; g -> f32 sigmoid)
    gemm_cp<<<dim3(NL / 128, 4), 512, GEMM_SMEM>>>(x, wt, bg, qh, kh, vh, g, 1);

    // 3) attention per (l, h) — fp16 mma
    attn_mma<<<LRES * NHEAD, 512, ATTN_SMEM>>>();

    // 4) output projection + bias
    gemm_cp<<<dim3(NL / 128, 1), 512, GEMM_SMEM>>>(o, wt, bo, out, nullptr, nullptr, nullptr, 0);
}